// round 11
// baseline (speedup 1.0000x reference)
#include <cuda_runtime.h>
#include <cuda_bf16.h>
#include <math.h>
#include <stdint.h>

#define IN_DIM   784
#define HIDDEN   512
#define STYLE    128
#define BATCH    2048
#define NUM_LABELS 10

#define BM 64
#define MAX_TILES (BATCH / BM + NUM_LABELS)   // 42
#define KSPLIT 4                              // fc2 K split: 512 / 4 = 128 per chunk

// Scratch (no allocations allowed -> __device__ globals)
__device__ int   g_perm[BATCH];
__device__ int   g_tileGroup[MAX_TILES];
__device__ int   g_tileStart[MAX_TILES];
__device__ int   g_tileRows[MAX_TILES];
__device__ int   g_tileDone[MAX_TILES];                          // fc2p arrival counters
__device__ __nv_bfloat16 g_h1[(BATCH + 128) * HIDDEN];           // padded
__device__ __nv_bfloat16 g_part[KSPLIT * BATCH * STYLE];         // fc2 partials, bf16, 2 MB

// ---------------------------------------------------------------------------
// Helpers
// ---------------------------------------------------------------------------
__device__ __forceinline__ uint32_t f2bf2(float lo, float hi) {
    __nv_bfloat162 h = __floats2bfloat162_rn(lo, hi);
    return *reinterpret_cast<uint32_t*>(&h);
}

__device__ __forceinline__ void ldsm_x4(uint32_t& r0, uint32_t& r1, uint32_t& r2, uint32_t& r3,
                                        uint32_t saddr) {
    asm volatile("ldmatrix.sync.aligned.m8n8.x4.shared.b16 {%0,%1,%2,%3}, [%4];"
                 : "=r"(r0), "=r"(r1), "=r"(r2), "=r"(r3) : "r"(saddr));
}

__device__ __forceinline__ void ldsm_x4_t(uint32_t& r0, uint32_t& r1, uint32_t& r2, uint32_t& r3,
                                          uint32_t saddr) {
    asm volatile("ldmatrix.sync.aligned.m8n8.x4.trans.shared.b16 {%0,%1,%2,%3}, [%4];"
                 : "=r"(r0), "=r"(r1), "=r"(r2), "=r"(r3) : "r"(saddr));
}

__device__ __forceinline__ void mma16816_c(float* c, const uint32_t* a, const uint32_t* b) {
    asm volatile("mma.sync.aligned.m16n8k16.row.col.f32.bf16.bf16.f32 "
                 "{%0,%1,%2,%3}, {%4,%5,%6,%7}, {%8,%9}, {%0,%1,%2,%3};"
                 : "+f"(c[0]), "+f"(c[1]), "+f"(c[2]), "+f"(c[3])
                 : "r"(a[0]), "r"(a[1]), "r"(a[2]), "r"(a[3]), "r"(b[0]), "r"(b[1]));
}

// ---------------------------------------------------------------------------
// Kernel 1: grouping, 32 blocks. Deterministic atomic-free counting sort,
// each block writes a disjoint slice of g_perm; block 0 writes the tile
// table AND resets the fc2p arrival counters (replay-safe).
// ---------------------------------------------------------------------------
__global__ void group_kernel(const int* __restrict__ m) {
    __shared__ uint16_t h[NUM_LABELS][257];
    __shared__ int cnt[NUM_LABELS];
    __shared__ int baseS[NUM_LABELS];
    const int t = threadIdx.x, lane = t & 31, warp = t >> 5;

    if (blockIdx.x == 0 && t < MAX_TILES) g_tileDone[t] = 0;

    int4 lv0 = ((const int4*)m)[t * 2];
    int4 lv1 = ((const int4*)m)[t * 2 + 1];
    int lab[8] = {lv0.x, lv0.y, lv0.z, lv0.w, lv1.x, lv1.y, lv1.z, lv1.w};

#pragma unroll
    for (int g = 0; g < NUM_LABELS; g++) {
        int c = 0;
#pragma unroll
        for (int j = 0; j < 8; j++) c += (lab[j] == g);
        h[g][t] = (uint16_t)c;
    }
    __syncthreads();

    for (int g = warp; g < NUM_LABELS; g += 8) {
        int s = 0;
#pragma unroll
        for (int j = 0; j < 8; j++) s += h[g][lane * 8 + j];
        int incl = s;
#pragma unroll
        for (int d = 1; d < 32; d <<= 1) {
            int v = __shfl_up_sync(0xffffffffu, incl, d);
            if (lane >= d) incl += v;
        }
        int run = incl - s;
#pragma unroll
        for (int j = 0; j < 8; j++) {
            int tt = lane * 8 + j;
            int v = h[g][tt];
            h[g][tt] = (uint16_t)run;
            run += v;
        }
        if (lane == 31) cnt[g] = run;
    }
    __syncthreads();

    if (t == 0) {
        int o = 0;
        for (int g = 0; g < NUM_LABELS; g++) { baseS[g] = o; o += cnt[g]; }
        if (blockIdx.x == 0) {                          // tile table
            int tile = 0;
            for (int g = 0; g < NUM_LABELS; g++) {
                int c = cnt[g], nt = (c + BM - 1) / BM;
                for (int j = 0; j < nt; j++) {
                    g_tileGroup[tile] = g;
                    g_tileStart[tile] = baseS[g] + j * BM;
                    g_tileRows[tile]  = min(BM, c - j * BM);
                    tile++;
                }
            }
            for (; tile < MAX_TILES; tile++) g_tileRows[tile] = 0;
        }
    }
    __syncthreads();

    if ((t >> 3) == (int)blockIdx.x) {                  // this block's 8 threads write
#pragma unroll
        for (int j = 0; j < 8; j++) {
            int g = lab[j];
            int rank = 0;
#pragma unroll
            for (int j2 = 0; j2 < 8; j2++)
                if (j2 < j) rank += (lab[j2] == g);
            g_perm[baseS[g] + (int)h[g][t] + rank] = t * 8 + j;
        }
    }
}

// ---------------------------------------------------------------------------
// Kernel 2: FC1 GEMM: 64x128 tile, BK=32, 256 thr, occ 2. (R5/R8 winner)
// ---------------------------------------------------------------------------
__global__ __launch_bounds__(256, 2) void fc1_kernel(const float* __restrict__ x,
                                                     const float* __restrict__ tab) {
    const int tile = blockIdx.y;
    const int rows = g_tileRows[tile];
    if (rows == 0) return;
    const int grp   = g_tileGroup[tile];
    const int start = g_tileStart[tile];
    const int n0    = blockIdx.x * 128;
    const float* W  = tab + (size_t)grp * ((IN_DIM + 1) * HIDDEN);

    __shared__ __align__(16) __nv_bfloat16 As[2][64][40];
    __shared__ __align__(16) __nv_bfloat16 Bs[2][32][136];
    __shared__ int rowIdx[64];

    const int t = threadIdx.x, lane = t & 31, warp = t >> 5;
    const int wm = warp >> 2, wn = warp & 3;

    if (t < 64) rowIdx[t] = (t < rows) ? g_perm[start + t] : -1;
    __syncthreads();

    int ar[2], ac4[2], alim[2]; const float* aptr[2];
#pragma unroll
    for (int p = 0; p < 2; p++) {
        int idx = t + p * 256;
        ar[p] = idx >> 3; ac4[p] = idx & 7;
        int gr = rowIdx[ar[p]];
        aptr[p] = x + (size_t)max(gr, 0) * IN_DIM + ac4[p] * 4;
        alim[p] = (gr >= 0) ? (IN_DIM - ac4[p] * 4) : 0;
    }
    int br[4], bc4[4];
#pragma unroll
    for (int p = 0; p < 4; p++) { int idx = t + p * 256; br[p] = idx >> 5; bc4[p] = idx & 31; }

    float acc[2][4][4];
#pragma unroll
    for (int mi = 0; mi < 2; mi++)
#pragma unroll
        for (int ni = 0; ni < 4; ni++)
#pragma unroll
            for (int j = 0; j < 4; j++) acc[mi][ni][j] = 0.f;

    const float4 Z4 = make_float4(0.f, 0.f, 0.f, 0.f);
    float4 aL[2], bL[4];
#pragma unroll
    for (int p = 0; p < 2; p++)
        aL[p] = (alim[p] > 0) ? *(const float4*)(aptr[p]) : Z4;
#pragma unroll
    for (int p = 0; p < 4; p++)
        bL[p] = *(const float4*)&W[(size_t)br[p] * HIDDEN + n0 + bc4[p] * 4];
#pragma unroll
    for (int p = 0; p < 2; p++) {
        *(uint32_t*)&As[0][ar[p]][ac4[p] * 4]     = f2bf2(aL[p].x, aL[p].y);
        *(uint32_t*)&As[0][ar[p]][ac4[p] * 4 + 2] = f2bf2(aL[p].z, aL[p].w);
    }
#pragma unroll
    for (int p = 0; p < 4; p++) {
        *(uint32_t*)&Bs[0][br[p]][bc4[p] * 4]     = f2bf2(bL[p].x, bL[p].y);
        *(uint32_t*)&Bs[0][br[p]][bc4[p] * 4 + 2] = f2bf2(bL[p].z, bL[p].w);
    }
    __syncthreads();

    const int NIT = (IN_DIM + 31) / 32;    // 25
    for (int it = 0; it < NIT; ++it) {
        const int cur = it & 1;
        if (it + 1 < NIT) {
            const int k0 = (it + 1) * 32;
#pragma unroll
            for (int p = 0; p < 2; p++)
                aL[p] = (k0 < alim[p]) ? *(const float4*)(aptr[p] + k0) : Z4;
#pragma unroll
            for (int p = 0; p < 4; p++) {
                int kr = k0 + br[p];
                const float4 v = *(const float4*)&W[(size_t)min(kr, IN_DIM) * HIDDEN + n0 + bc4[p] * 4];
                bL[p] = (kr < IN_DIM) ? v : Z4;
            }
        }

        uint32_t a[2][2][4], b[2][4][2];
#pragma unroll
        for (int mi = 0; mi < 2; mi++)
#pragma unroll
            for (int kh = 0; kh < 2; kh++) {
                uint32_t sa = (uint32_t)__cvta_generic_to_shared(
                    &As[cur][wm * 32 + mi * 16 + (lane & 15)][kh * 16 + (lane >> 4) * 8]);
                ldsm_x4(a[mi][kh][0], a[mi][kh][1], a[mi][kh][2], a[mi][kh][3], sa);
            }
#pragma unroll
        for (int kh = 0; kh < 2; kh++)
#pragma unroll
            for (int half = 0; half < 2; half++) {
                uint32_t sb = (uint32_t)__cvta_generic_to_shared(
                    &Bs[cur][kh * 16 + (lane & 7) + ((lane >> 3) & 1) * 8]
                       [wn * 32 + half * 16 + (lane >> 4) * 8]);
                ldsm_x4_t(b[kh][2 * half][0], b[kh][2 * half][1],
                          b[kh][2 * half + 1][0], b[kh][2 * half + 1][1], sb);
            }
#pragma unroll
        for (int kh = 0; kh < 2; kh++)
#pragma unroll
            for (int mi = 0; mi < 2; mi++)
#pragma unroll
                for (int ni = 0; ni < 4; ni++)
                    mma16816_c(acc[mi][ni], a[mi][kh], b[kh][ni]);

        if (it + 1 < NIT) {
            const int nxt = cur ^ 1;
#pragma unroll
            for (int p = 0; p < 2; p++) {
                *(uint32_t*)&As[nxt][ar[p]][ac4[p] * 4]     = f2bf2(aL[p].x, aL[p].y);
                *(uint32_t*)&As[nxt][ar[p]][ac4[p] * 4 + 2] = f2bf2(aL[p].z, aL[p].w);
            }
#pragma unroll
            for (int p = 0; p < 4; p++) {
                *(uint32_t*)&Bs[nxt][br[p]][bc4[p] * 4]     = f2bf2(bL[p].x, bL[p].y);
                *(uint32_t*)&Bs[nxt][br[p]][bc4[p] * 4 + 2] = f2bf2(bL[p].z, bL[p].w);
            }
        }
        __syncthreads();
    }

    const float* bias = W + (size_t)IN_DIM * HIDDEN + n0;
    uint32_t* h1u = (uint32_t*)g_h1;
#pragma unroll
    for (int ni = 0; ni < 4; ni++) {
        int c = wn * 32 + ni * 8 + (lane & 3) * 2;
        float2 bb = *(const float2*)&bias[c];
#pragma unroll
        for (int mi = 0; mi < 2; mi++) {
            int r0 = wm * 32 + mi * 16 + (lane >> 2);
            if (r0 < rows) {
                float vx = fmaxf(acc[mi][ni][0] + bb.x, 0.f);
                float vy = fmaxf(acc[mi][ni][1] + bb.y, 0.f);
                h1u[((size_t)(start + r0) * HIDDEN + n0 + c) >> 1] = f2bf2(vx, vy);
            }
            int r1 = r0 + 8;
            if (r1 < rows) {
                float vx = fmaxf(acc[mi][ni][2] + bb.x, 0.f);
                float vy = fmaxf(acc[mi][ni][3] + bb.y, 0.f);
                h1u[((size_t)(start + r1) * HIDDEN + n0 + c) >> 1] = f2bf2(vx, vy);
            }
        }
    }
}

// ---------------------------------------------------------------------------
// Kernel 3: FC2 split-K partial + FUSED combine tail.
// grid (42 tiles, 4 kchunks). Each block computes a 64x128 partial (K=128)
// and stores bf16 partials. The LAST arriving block per tile (per-tile atomic
// counter) reads all 4 partials (L2-hot), adds bias, applies sigmoid, and
// scatters to out. Fixed k-order summation -> deterministic.
// ---------------------------------------------------------------------------
__global__ __launch_bounds__(256, 2) void fc2p_kernel(const float* __restrict__ tab,
                                                      float*       __restrict__ out) {
    const int tile = blockIdx.x;
    const int kc   = blockIdx.y;
    const int rows = g_tileRows[tile];
    if (rows == 0) return;
    const int grp   = g_tileGroup[tile];
    const int start = g_tileStart[tile];
    const float* Wt = tab + (size_t)grp * ((HIDDEN + 1) * STYLE);
    const float* W  = Wt + (size_t)(kc * 128) * STYLE;

    __shared__ __align__(16) __nv_bfloat16 As[64][136];
    __shared__ __align__(16) __nv_bfloat16 Bs[64][136];
    __shared__ int rowIdxS[64];
    __shared__ int lastFlag;

    const int t = threadIdx.x, lane = t & 31, warp = t >> 5;
    const int wm = warp >> 2, wn = warp & 3;

    {
        const __nv_bfloat16* h1 = g_h1 + (size_t)start * HIDDEN + kc * 128;
#pragma unroll
        for (int p = 0; p < 2; p++) {
            int idx = t + p * 256;
            int r = idx >> 3, q = idx & 7;
            *(uint4*)&As[r][q * 8] = *(const uint4*)(h1 + (size_t)r * HIDDEN + q * 8);
        }
    }

    float acc[2][4][4];
#pragma unroll
    for (int mi = 0; mi < 2; mi++)
#pragma unroll
        for (int ni = 0; ni < 4; ni++)
#pragma unroll
            for (int j = 0; j < 4; j++) acc[mi][ni][j] = 0.f;

#pragma unroll
    for (int h2 = 0; h2 < 2; h2++) {
#pragma unroll
        for (int p = 0; p < 8; p++) {
            int idx = t + p * 256;
            int r = idx >> 5, c4 = idx & 31;
            float4 v = *(const float4*)&W[(size_t)(h2 * 64 + r) * STYLE + c4 * 4];
            *(uint32_t*)&Bs[r][c4 * 4]     = f2bf2(v.x, v.y);
            *(uint32_t*)&Bs[r][c4 * 4 + 2] = f2bf2(v.z, v.w);
        }
        __syncthreads();

#pragma unroll
        for (int kh = 0; kh < 4; kh++) {
            uint32_t a[2][4], b[4][2];
#pragma unroll
            for (int mi = 0; mi < 2; mi++) {
                uint32_t sa = (uint32_t)__cvta_generic_to_shared(
                    &As[wm * 32 + mi * 16 + (lane & 15)][h2 * 64 + kh * 16 + (lane >> 4) * 8]);
                ldsm_x4(a[mi][0], a[mi][1], a[mi][2], a[mi][3], sa);
            }
#pragma unroll
            for (int half = 0; half < 2; half++) {
                uint32_t sb = (uint32_t)__cvta_generic_to_shared(
                    &Bs[kh * 16 + (lane & 7) + ((lane >> 3) & 1) * 8]
                       [wn * 32 + half * 16 + (lane >> 4) * 8]);
                ldsm_x4_t(b[2 * half][0], b[2 * half][1], b[2 * half + 1][0], b[2 * half + 1][1], sb);
            }
#pragma unroll
            for (int mi = 0; mi < 2; mi++)
#pragma unroll
                for (int ni = 0; ni < 4; ni++)
                    mma16816_c(acc[mi][ni], a[mi], b[ni]);
        }
        __syncthreads();
    }

    // Store bf16 partials (permuted dense rows)
    __nv_bfloat16* P = g_part + (size_t)kc * BATCH * STYLE;
#pragma unroll
    for (int ni = 0; ni < 4; ni++) {
        int c = wn * 32 + ni * 8 + (lane & 3) * 2;
#pragma unroll
        for (int mi = 0; mi < 2; mi++) {
            int r0 = wm * 32 + mi * 16 + (lane >> 2);
            if (r0 < rows)
                *(uint32_t*)&P[(size_t)(start + r0) * STYLE + c] =
                    f2bf2(acc[mi][ni][0], acc[mi][ni][1]);
            int r1 = r0 + 8;
            if (r1 < rows)
                *(uint32_t*)&P[(size_t)(start + r1) * STYLE + c] =
                    f2bf2(acc[mi][ni][2], acc[mi][ni][3]);
        }
    }

    // ---- arrival counter: last block per tile does the combine ------------
    __threadfence();                                    // partials visible before count
    if (t == 0)
        lastFlag = (atomicAdd(&g_tileDone[tile], 1) == KSPLIT - 1) ? 1 : 0;
    __syncthreads();
    if (!lastFlag) return;
    __threadfence();                                    // acquire: counts -> partial reads

    if (t < 64) rowIdxS[t] = (t < rows) ? g_perm[start + t] : 0;
    __syncthreads();

    const float* bias = Wt + (size_t)HIDDEN * STYLE;
#pragma unroll
    for (int p = 0; p < 4; p++) {
        int i = t + p * 256;                            // 0 .. 1023
        int r = i >> 4;                                 // row 0..63
        int q = i & 15;                                 // uint4 col (8 bf16 = cols q*8..)
        if (r < rows) {
            size_t off = (size_t)(start + r) * STYLE + q * 8;
            float s[8] = {0.f, 0.f, 0.f, 0.f, 0.f, 0.f, 0.f, 0.f};
#pragma unroll
            for (int k = 0; k < KSPLIT; k++) {
                uint4 vv = __ldcg((const uint4*)(g_part + (size_t)k * BATCH * STYLE + off));
                const __nv_bfloat162* pv = (const __nv_bfloat162*)&vv;
#pragma unroll
                for (int j = 0; j < 4; j++) {
                    float2 f = __bfloat1622float2(pv[j]);
                    s[2 * j]     += f.x;
                    s[2 * j + 1] += f.y;
                }
            }
            float4 b0 = *(const float4*)&bias[q * 8];
            float4 b1 = *(const float4*)&bias[q * 8 + 4];
            float* op = out + (size_t)rowIdxS[r] * STYLE + q * 8;
            *(float4*)op = make_float4(
                1.f / (1.f + __expf(-(s[0] + b0.x))),
                1.f / (1.f + __expf(-(s[1] + b0.y))),
                1.f / (1.f + __expf(-(s[2] + b0.z))),
                1.f / (1.f + __expf(-(s[3] + b0.w))));
            *(float4*)(op + 4) = make_float4(
                1.f / (1.f + __expf(-(s[4] + b1.x))),
                1.f / (1.f + __expf(-(s[5] + b1.y))),
                1.f / (1.f + __expf(-(s[6] + b1.z))),
                1.f / (1.f + __expf(-(s[7] + b1.w))));
        }
    }
}

extern "C" void kernel_launch(void* const* d_in, const int* in_sizes, int n_in,
                              void* d_out, int out_size) {
    const float* x         = (const float*)d_in[0];
    const int*   m         = (const int*)d_in[1];
    const float* fc1_table = (const float*)d_in[2];
    const float* fc2_table = (const float*)d_in[3];
    float*       out       = (float*)d_out;

    group_kernel<<<32, 256>>>(m);
    fc1_kernel<<<dim3(HIDDEN / 128, MAX_TILES), 256>>>(x, fc1_table);
    fc2p_kernel<<<dim3(MAX_TILES, KSPLIT), 256>>>(fc2_table, out);
}

// round 12
// speedup vs baseline: 1.5672x; 1.5672x over previous
#include <cuda_runtime.h>
#include <cuda_bf16.h>
#include <math.h>
#include <stdint.h>

#define IN_DIM   784
#define HIDDEN   512
#define STYLE    128
#define BATCH    2048
#define NUM_LABELS 10

#define BM 64
#define MAX_TILES (BATCH / BM + NUM_LABELS)   // 42
#define KSPLIT 4                              // fc2 K split: 512 / 4 = 128 per chunk

// Scratch (no allocations allowed -> __device__ globals)
__device__ int   g_perm[BATCH];
__device__ int   g_tileGroup[MAX_TILES];
__device__ int   g_tileStart[MAX_TILES];
__device__ int   g_tileRows[MAX_TILES];
__device__ int   g_ready;                                        // grouping publish flag
__device__ __nv_bfloat16 g_h1[(BATCH + 128) * HIDDEN];           // padded
__device__ __nv_bfloat16 g_part[KSPLIT * BATCH * STYLE];         // fc2 partials, bf16, 2 MB

// ---------------------------------------------------------------------------
// Helpers
// ---------------------------------------------------------------------------
__device__ __forceinline__ uint32_t f2bf2(float lo, float hi) {
    __nv_bfloat162 h = __floats2bfloat162_rn(lo, hi);
    return *reinterpret_cast<uint32_t*>(&h);
}

__device__ __forceinline__ void ldsm_x4(uint32_t& r0, uint32_t& r1, uint32_t& r2, uint32_t& r3,
                                        uint32_t saddr) {
    asm volatile("ldmatrix.sync.aligned.m8n8.x4.shared.b16 {%0,%1,%2,%3}, [%4];"
                 : "=r"(r0), "=r"(r1), "=r"(r2), "=r"(r3) : "r"(saddr));
}

__device__ __forceinline__ void ldsm_x4_t(uint32_t& r0, uint32_t& r1, uint32_t& r2, uint32_t& r3,
                                          uint32_t saddr) {
    asm volatile("ldmatrix.sync.aligned.m8n8.x4.trans.shared.b16 {%0,%1,%2,%3}, [%4];"
                 : "=r"(r0), "=r"(r1), "=r"(r2), "=r"(r3) : "r"(saddr));
}

__device__ __forceinline__ void mma16816_c(float* c, const uint32_t* a, const uint32_t* b) {
    asm volatile("mma.sync.aligned.m16n8k16.row.col.f32.bf16.bf16.f32 "
                 "{%0,%1,%2,%3}, {%4,%5,%6,%7}, {%8,%9}, {%0,%1,%2,%3};"
                 : "+f"(c[0]), "+f"(c[1]), "+f"(c[2]), "+f"(c[3])
                 : "r"(a[0]), "r"(a[1]), "r"(a[2]), "r"(a[3]), "r"(b[0]), "r"(b[1]));
}

// ---------------------------------------------------------------------------
// Kernel 1: FC1 GEMM (64x128 tile, BK=32, 256 thr, occ 2 — R5/R8 winner,
// untouched) + ONE dedicated grouping block.
// Grid (4, 43): block (0,42) runs the deterministic atomic-free counting
// sort (aliased into its own smem) and publishes g_perm + tile table, then
// sets g_ready. Blocks (x>0,42) exit. The 168 GEMM blocks spin on g_ready
// (1 poller/block, nanosleep backoff) before touching the tables — their
// GEMM code path is byte-identical to R10.
// ---------------------------------------------------------------------------
__global__ __launch_bounds__(256, 2) void fc1_kernel(const float* __restrict__ x,
                                                     const int*   __restrict__ m,
                                                     const float* __restrict__ tab) {
    __shared__ __align__(16) __nv_bfloat16 As[2][64][40];    // 10.0 KB
    __shared__ __align__(16) __nv_bfloat16 Bs[2][32][136];   // 17.0 KB
    __shared__ int rowIdx[64];
    __shared__ int cntS[NUM_LABELS];
    __shared__ int baseS[NUM_LABELS];

    const int t = threadIdx.x, lane = t & 31, warp = t >> 5;

    // ==== dedicated grouping block =========================================
    if (blockIdx.y == MAX_TILES) {
        if (blockIdx.x != 0) return;
        // histogram aliased onto As (5140 B < 10240 B)
        uint16_t (*h)[257] = reinterpret_cast<uint16_t(*)[257]>(&As[0][0][0]);

        int4 lv0 = ((const int4*)m)[t * 2];
        int4 lv1 = ((const int4*)m)[t * 2 + 1];
        int lab[8] = {lv0.x, lv0.y, lv0.z, lv0.w, lv1.x, lv1.y, lv1.z, lv1.w};

#pragma unroll
        for (int g = 0; g < NUM_LABELS; g++) {
            int c = 0;
#pragma unroll
            for (int j = 0; j < 8; j++) c += (lab[j] == g);
            h[g][t] = (uint16_t)c;
        }
        __syncthreads();

        for (int g = warp; g < NUM_LABELS; g += 8) {
            int s = 0;
#pragma unroll
            for (int j = 0; j < 8; j++) s += h[g][lane * 8 + j];
            int incl = s;
#pragma unroll
            for (int d = 1; d < 32; d <<= 1) {
                int v = __shfl_up_sync(0xffffffffu, incl, d);
                if (lane >= d) incl += v;
            }
            int run = incl - s;
#pragma unroll
            for (int j = 0; j < 8; j++) {
                int tt = lane * 8 + j;
                int v = h[g][tt];
                h[g][tt] = (uint16_t)run;
                run += v;
            }
            if (lane == 31) cntS[g] = run;
        }
        __syncthreads();

        if (t == 0) {
            int o = 0;
            for (int g = 0; g < NUM_LABELS; g++) { baseS[g] = o; o += cntS[g]; }
            int tile = 0;
            for (int g = 0; g < NUM_LABELS; g++) {
                int c = cntS[g], nt = (c + BM - 1) / BM;
                for (int j = 0; j < nt; j++) {
                    g_tileGroup[tile] = g;
                    g_tileStart[tile] = baseS[g] + j * BM;
                    g_tileRows[tile]  = min(BM, c - j * BM);
                    tile++;
                }
            }
            for (; tile < MAX_TILES; tile++) g_tileRows[tile] = 0;
        }
        __syncthreads();

#pragma unroll
        for (int j = 0; j < 8; j++) {
            int g = lab[j];
            int rank = 0;
#pragma unroll
            for (int j2 = 0; j2 < 8; j2++)
                if (j2 < j) rank += (lab[j2] == g);
            g_perm[baseS[g] + (int)h[g][t] + rank] = t * 8 + j;
        }

        __threadfence();                 // each thread's global writes visible
        __syncthreads();
        if (t == 0) atomicExch(&g_ready, 1);
        return;
    }

    // ==== GEMM blocks: gate on grouping publish ============================
    if (t == 0) {
        while (atomicAdd(&g_ready, 0) == 0) __nanosleep(64);
    }
    __syncthreads();

    const int tile = blockIdx.y;
    const int rows = g_tileRows[tile];
    if (rows == 0) return;
    const int grp   = g_tileGroup[tile];
    const int start = g_tileStart[tile];
    const int n0    = blockIdx.x * 128;
    const float* W  = tab + (size_t)grp * ((IN_DIM + 1) * HIDDEN);

    const int wm = warp >> 2, wn = warp & 3;

    if (t < 64) rowIdx[t] = (t < rows) ? g_perm[start + t] : -1;
    __syncthreads();

    int ar[2], ac4[2], alim[2]; const float* aptr[2];
#pragma unroll
    for (int p = 0; p < 2; p++) {
        int idx = t + p * 256;
        ar[p] = idx >> 3; ac4[p] = idx & 7;
        int gr = rowIdx[ar[p]];
        aptr[p] = x + (size_t)max(gr, 0) * IN_DIM + ac4[p] * 4;
        alim[p] = (gr >= 0) ? (IN_DIM - ac4[p] * 4) : 0;
    }
    int br[4], bc4[4];
#pragma unroll
    for (int p = 0; p < 4; p++) { int idx = t + p * 256; br[p] = idx >> 5; bc4[p] = idx & 31; }

    float acc[2][4][4];
#pragma unroll
    for (int mi = 0; mi < 2; mi++)
#pragma unroll
        for (int ni = 0; ni < 4; ni++)
#pragma unroll
            for (int j = 0; j < 4; j++) acc[mi][ni][j] = 0.f;

    const float4 Z4 = make_float4(0.f, 0.f, 0.f, 0.f);
    float4 aL[2], bL[4];
#pragma unroll
    for (int p = 0; p < 2; p++)
        aL[p] = (alim[p] > 0) ? *(const float4*)(aptr[p]) : Z4;
#pragma unroll
    for (int p = 0; p < 4; p++)
        bL[p] = *(const float4*)&W[(size_t)br[p] * HIDDEN + n0 + bc4[p] * 4];
#pragma unroll
    for (int p = 0; p < 2; p++) {
        *(uint32_t*)&As[0][ar[p]][ac4[p] * 4]     = f2bf2(aL[p].x, aL[p].y);
        *(uint32_t*)&As[0][ar[p]][ac4[p] * 4 + 2] = f2bf2(aL[p].z, aL[p].w);
    }
#pragma unroll
    for (int p = 0; p < 4; p++) {
        *(uint32_t*)&Bs[0][br[p]][bc4[p] * 4]     = f2bf2(bL[p].x, bL[p].y);
        *(uint32_t*)&Bs[0][br[p]][bc4[p] * 4 + 2] = f2bf2(bL[p].z, bL[p].w);
    }
    __syncthreads();

    const int NIT = (IN_DIM + 31) / 32;    // 25
    for (int it = 0; it < NIT; ++it) {
        const int cur = it & 1;
        if (it + 1 < NIT) {
            const int k0 = (it + 1) * 32;
#pragma unroll
            for (int p = 0; p < 2; p++)
                aL[p] = (k0 < alim[p]) ? *(const float4*)(aptr[p] + k0) : Z4;
#pragma unroll
            for (int p = 0; p < 4; p++) {
                int kr = k0 + br[p];
                const float4 v = *(const float4*)&W[(size_t)min(kr, IN_DIM) * HIDDEN + n0 + bc4[p] * 4];
                bL[p] = (kr < IN_DIM) ? v : Z4;
            }
        }

        uint32_t a[2][2][4], b[2][4][2];
#pragma unroll
        for (int mi = 0; mi < 2; mi++)
#pragma unroll
            for (int kh = 0; kh < 2; kh++) {
                uint32_t sa = (uint32_t)__cvta_generic_to_shared(
                    &As[cur][wm * 32 + mi * 16 + (lane & 15)][kh * 16 + (lane >> 4) * 8]);
                ldsm_x4(a[mi][kh][0], a[mi][kh][1], a[mi][kh][2], a[mi][kh][3], sa);
            }
#pragma unroll
        for (int kh = 0; kh < 2; kh++)
#pragma unroll
            for (int half = 0; half < 2; half++) {
                uint32_t sb = (uint32_t)__cvta_generic_to_shared(
                    &Bs[cur][kh * 16 + (lane & 7) + ((lane >> 3) & 1) * 8]
                       [wn * 32 + half * 16 + (lane >> 4) * 8]);
                ldsm_x4_t(b[kh][2 * half][0], b[kh][2 * half][1],
                          b[kh][2 * half + 1][0], b[kh][2 * half + 1][1], sb);
            }
#pragma unroll
        for (int kh = 0; kh < 2; kh++)
#pragma unroll
            for (int mi = 0; mi < 2; mi++)
#pragma unroll
                for (int ni = 0; ni < 4; ni++)
                    mma16816_c(acc[mi][ni], a[mi][kh], b[kh][ni]);

        if (it + 1 < NIT) {
            const int nxt = cur ^ 1;
#pragma unroll
            for (int p = 0; p < 2; p++) {
                *(uint32_t*)&As[nxt][ar[p]][ac4[p] * 4]     = f2bf2(aL[p].x, aL[p].y);
                *(uint32_t*)&As[nxt][ar[p]][ac4[p] * 4 + 2] = f2bf2(aL[p].z, aL[p].w);
            }
#pragma unroll
            for (int p = 0; p < 4; p++) {
                *(uint32_t*)&Bs[nxt][br[p]][bc4[p] * 4]     = f2bf2(bL[p].x, bL[p].y);
                *(uint32_t*)&Bs[nxt][br[p]][bc4[p] * 4 + 2] = f2bf2(bL[p].z, bL[p].w);
            }
        }
        __syncthreads();
    }

    const float* bias = W + (size_t)IN_DIM * HIDDEN + n0;
    uint32_t* h1u = (uint32_t*)g_h1;
#pragma unroll
    for (int ni = 0; ni < 4; ni++) {
        int c = wn * 32 + ni * 8 + (lane & 3) * 2;
        float2 bb = *(const float2*)&bias[c];
#pragma unroll
        for (int mi = 0; mi < 2; mi++) {
            int r0 = wm * 32 + mi * 16 + (lane >> 2);
            if (r0 < rows) {
                float vx = fmaxf(acc[mi][ni][0] + bb.x, 0.f);
                float vy = fmaxf(acc[mi][ni][1] + bb.y, 0.f);
                h1u[((size_t)(start + r0) * HIDDEN + n0 + c) >> 1] = f2bf2(vx, vy);
            }
            int r1 = r0 + 8;
            if (r1 < rows) {
                float vx = fmaxf(acc[mi][ni][2] + bb.x, 0.f);
                float vy = fmaxf(acc[mi][ni][3] + bb.y, 0.f);
                h1u[((size_t)(start + r1) * HIDDEN + n0 + c) >> 1] = f2bf2(vx, vy);
            }
        }
    }
}

// ---------------------------------------------------------------------------
// Kernel 2: FC2 split-K partial (R10, unchanged). grid (42, 4).
// ---------------------------------------------------------------------------
__global__ __launch_bounds__(256, 2) void fc2p_kernel(const float* __restrict__ tab) {
    const int tile = blockIdx.x;
    const int kc   = blockIdx.y;
    const int rows = g_tileRows[tile];
    if (rows == 0) return;
    const int grp   = g_tileGroup[tile];
    const int start = g_tileStart[tile];
    const float* W  = tab + (size_t)grp * ((HIDDEN + 1) * STYLE) + (size_t)(kc * 128) * STYLE;

    __shared__ __align__(16) __nv_bfloat16 As[64][136];
    __shared__ __align__(16) __nv_bfloat16 Bs[64][136];

    const int t = threadIdx.x, lane = t & 31, warp = t >> 5;
    const int wm = warp >> 2, wn = warp & 3;

    {
        const __nv_bfloat16* h1 = g_h1 + (size_t)start * HIDDEN + kc * 128;
#pragma unroll
        for (int p = 0; p < 2; p++) {
            int idx = t + p * 256;
            int r = idx >> 3, q = idx & 7;
            *(uint4*)&As[r][q * 8] = *(const uint4*)(h1 + (size_t)r * HIDDEN + q * 8);
        }
    }

    float acc[2][4][4];
#pragma unroll
    for (int mi = 0; mi < 2; mi++)
#pragma unroll
        for (int ni = 0; ni < 4; ni++)
#pragma unroll
            for (int j = 0; j < 4; j++) acc[mi][ni][j] = 0.f;

#pragma unroll
    for (int h2 = 0; h2 < 2; h2++) {
#pragma unroll
        for (int p = 0; p < 8; p++) {
            int idx = t + p * 256;
            int r = idx >> 5, c4 = idx & 31;
            float4 v = *(const float4*)&W[(size_t)(h2 * 64 + r) * STYLE + c4 * 4];
            *(uint32_t*)&Bs[r][c4 * 4]     = f2bf2(v.x, v.y);
            *(uint32_t*)&Bs[r][c4 * 4 + 2] = f2bf2(v.z, v.w);
        }
        __syncthreads();

#pragma unroll
        for (int kh = 0; kh < 4; kh++) {
            uint32_t a[2][4], b[4][2];
#pragma unroll
            for (int mi = 0; mi < 2; mi++) {
                uint32_t sa = (uint32_t)__cvta_generic_to_shared(
                    &As[wm * 32 + mi * 16 + (lane & 15)][h2 * 64 + kh * 16 + (lane >> 4) * 8]);
                ldsm_x4(a[mi][0], a[mi][1], a[mi][2], a[mi][3], sa);
            }
#pragma unroll
            for (int half = 0; half < 2; half++) {
                uint32_t sb = (uint32_t)__cvta_generic_to_shared(
                    &Bs[kh * 16 + (lane & 7) + ((lane >> 3) & 1) * 8]
                       [wn * 32 + half * 16 + (lane >> 4) * 8]);
                ldsm_x4_t(b[2 * half][0], b[2 * half][1], b[2 * half + 1][0], b[2 * half + 1][1], sb);
            }
#pragma unroll
            for (int mi = 0; mi < 2; mi++)
#pragma unroll
                for (int ni = 0; ni < 4; ni++)
                    mma16816_c(acc[mi][ni], a[mi], b[ni]);
        }
        __syncthreads();
    }

    __nv_bfloat16* P = g_part + (size_t)kc * BATCH * STYLE;
#pragma unroll
    for (int ni = 0; ni < 4; ni++) {
        int c = wn * 32 + ni * 8 + (lane & 3) * 2;
#pragma unroll
        for (int mi = 0; mi < 2; mi++) {
            int r0 = wm * 32 + mi * 16 + (lane >> 2);
            if (r0 < rows)
                *(uint32_t*)&P[(size_t)(start + r0) * STYLE + c] =
                    f2bf2(acc[mi][ni][0], acc[mi][ni][1]);
            int r1 = r0 + 8;
            if (r1 < rows)
                *(uint32_t*)&P[(size_t)(start + r1) * STYLE + c] =
                    f2bf2(acc[mi][ni][2], acc[mi][ni][3]);
        }
    }
}

// ---------------------------------------------------------------------------
// Kernel 3: FLAT combine (R10, unchanged) + g_ready reset for next replay.
// ---------------------------------------------------------------------------
__global__ __launch_bounds__(256) void combine_kernel(const int*   __restrict__ m,
                                                      const float* __restrict__ tab,
                                                      float*       __restrict__ out) {
    if (blockIdx.x == 0 && threadIdx.x == 0) g_ready = 0;   // fc1 already done (stream order)

    const int idx = blockIdx.x * 256 + threadIdx.x;     // 0 .. BATCH*32-1
    const int pos = idx >> 5;                           // permuted row
    const int c4  = idx & 31;                           // float4 column

    const int orow = g_perm[pos];                       // warp-broadcast
    const int grp  = m[orow];
    const float* bias = tab + (size_t)grp * ((HIDDEN + 1) * STYLE) + (size_t)HIDDEN * STYLE;
    float4 bb = *(const float4*)&bias[c4 * 4];

    const __nv_bfloat162* P = (const __nv_bfloat162*)g_part;
    const size_t off2 = ((size_t)pos * STYLE + c4 * 4) >> 1;   // bf16x2 index
    float2 sA = make_float2(0.f, 0.f), sB = make_float2(0.f, 0.f);
#pragma unroll
    for (int k = 0; k < KSPLIT; k++) {
        const __nv_bfloat162* Pk = P + (size_t)k * (BATCH * STYLE / 2);
        float2 p0 = __bfloat1622float2(Pk[off2]);
        float2 p1 = __bfloat1622float2(Pk[off2 + 1]);
        sA.x += p0.x; sA.y += p0.y;
        sB.x += p1.x; sB.y += p1.y;
    }
    float4 v;
    v.x = 1.f / (1.f + __expf(-(sA.x + bb.x)));
    v.y = 1.f / (1.f + __expf(-(sA.y + bb.y)));
    v.z = 1.f / (1.f + __expf(-(sB.x + bb.z)));
    v.w = 1.f / (1.f + __expf(-(sB.y + bb.w)));
    *(float4*)&out[(size_t)orow * STYLE + c4 * 4] = v;
}

extern "C" void kernel_launch(void* const* d_in, const int* in_sizes, int n_in,
                              void* d_out, int out_size) {
    const float* x         = (const float*)d_in[0];
    const int*   m         = (const int*)d_in[1];
    const float* fc1_table = (const float*)d_in[2];
    const float* fc2_table = (const float*)d_in[3];
    float*       out       = (float*)d_out;

    fc1_kernel<<<dim3(HIDDEN / 128, MAX_TILES + 1), 256>>>(x, m, fc1_table);
    fc2p_kernel<<<dim3(MAX_TILES, KSPLIT), 256>>>(fc2_table);
    combine_kernel<<<(BATCH * 32) / 256, 256>>>(m, fc2_table, out);
}

// round 13
// speedup vs baseline: 1.5768x; 1.0061x over previous
#include <cuda_runtime.h>
#include <cuda_bf16.h>
#include <math.h>
#include <stdint.h>

#define IN_DIM   784
#define HIDDEN   512
#define STYLE    128
#define BATCH    2048
#define NUM_LABELS 10

#define BM 64
#define MAX_TILES (BATCH / BM + NUM_LABELS)   // 42
#define KSPLIT 4                              // fc2 K split: 512 / 4 = 128 per chunk
#define FC2_BLOCKS (MAX_TILES * KSPLIT)       // 168

// Scratch (no allocations allowed -> __device__ globals)
__device__ int   g_perm[BATCH];
__device__ int   g_tileGroup[MAX_TILES];
__device__ int   g_tileStart[MAX_TILES];
__device__ int   g_tileRows[MAX_TILES];
__device__ int   g_done;                                         // fc2p arrival counter
__device__ __nv_bfloat16 g_h1[(BATCH + 128) * HIDDEN];           // padded
__device__ __nv_bfloat16 g_part[KSPLIT * BATCH * STYLE];         // fc2 partials, bf16, 2 MB

// ---------------------------------------------------------------------------
// Helpers
// ---------------------------------------------------------------------------
__device__ __forceinline__ uint32_t f2bf2(float lo, float hi) {
    __nv_bfloat162 h = __floats2bfloat162_rn(lo, hi);
    return *reinterpret_cast<uint32_t*>(&h);
}

__device__ __forceinline__ void ldsm_x4(uint32_t& r0, uint32_t& r1, uint32_t& r2, uint32_t& r3,
                                        uint32_t saddr) {
    asm volatile("ldmatrix.sync.aligned.m8n8.x4.shared.b16 {%0,%1,%2,%3}, [%4];"
                 : "=r"(r0), "=r"(r1), "=r"(r2), "=r"(r3) : "r"(saddr));
}

__device__ __forceinline__ void ldsm_x4_t(uint32_t& r0, uint32_t& r1, uint32_t& r2, uint32_t& r3,
                                          uint32_t saddr) {
    asm volatile("ldmatrix.sync.aligned.m8n8.x4.trans.shared.b16 {%0,%1,%2,%3}, [%4];"
                 : "=r"(r0), "=r"(r1), "=r"(r2), "=r"(r3) : "r"(saddr));
}

__device__ __forceinline__ void mma16816_c(float* c, const uint32_t* a, const uint32_t* b) {
    asm volatile("mma.sync.aligned.m16n8k16.row.col.f32.bf16.bf16.f32 "
                 "{%0,%1,%2,%3}, {%4,%5,%6,%7}, {%8,%9}, {%0,%1,%2,%3};"
                 : "+f"(c[0]), "+f"(c[1]), "+f"(c[2]), "+f"(c[3])
                 : "r"(a[0]), "r"(a[1]), "r"(a[2]), "r"(a[3]), "r"(b[0]), "r"(b[1]));
}

// ---------------------------------------------------------------------------
// Kernel 1: grouping, 32 blocks (R8 version) + arrival-counter reset.
// Deterministic atomic-free counting sort; block b writes perm slice b;
// block 0 writes the tile table and resets g_done (replay-safe).
// ---------------------------------------------------------------------------
__global__ void group_kernel(const int* __restrict__ m) {
    __shared__ uint16_t h[NUM_LABELS][257];
    __shared__ int cnt[NUM_LABELS];
    __shared__ int baseS[NUM_LABELS];
    const int t = threadIdx.x, lane = t & 31, warp = t >> 5;

    if (blockIdx.x == 0 && t == 0) g_done = 0;

    int4 lv0 = ((const int4*)m)[t * 2];
    int4 lv1 = ((const int4*)m)[t * 2 + 1];
    int lab[8] = {lv0.x, lv0.y, lv0.z, lv0.w, lv1.x, lv1.y, lv1.z, lv1.w};

#pragma unroll
    for (int g = 0; g < NUM_LABELS; g++) {
        int c = 0;
#pragma unroll
        for (int j = 0; j < 8; j++) c += (lab[j] == g);
        h[g][t] = (uint16_t)c;
    }
    __syncthreads();

    for (int g = warp; g < NUM_LABELS; g += 8) {
        int s = 0;
#pragma unroll
        for (int j = 0; j < 8; j++) s += h[g][lane * 8 + j];
        int incl = s;
#pragma unroll
        for (int d = 1; d < 32; d <<= 1) {
            int v = __shfl_up_sync(0xffffffffu, incl, d);
            if (lane >= d) incl += v;
        }
        int run = incl - s;
#pragma unroll
        for (int j = 0; j < 8; j++) {
            int tt = lane * 8 + j;
            int v = h[g][tt];
            h[g][tt] = (uint16_t)run;
            run += v;
        }
        if (lane == 31) cnt[g] = run;
    }
    __syncthreads();

    if (t == 0) {
        int o = 0;
        for (int g = 0; g < NUM_LABELS; g++) { baseS[g] = o; o += cnt[g]; }
        if (blockIdx.x == 0) {                          // tile table
            int tile = 0;
            for (int g = 0; g < NUM_LABELS; g++) {
                int c = cnt[g], nt = (c + BM - 1) / BM;
                for (int j = 0; j < nt; j++) {
                    g_tileGroup[tile] = g;
                    g_tileStart[tile] = baseS[g] + j * BM;
                    g_tileRows[tile]  = min(BM, c - j * BM);
                    tile++;
                }
            }
            for (; tile < MAX_TILES; tile++) g_tileRows[tile] = 0;
        }
    }
    __syncthreads();

    if ((t >> 3) == (int)blockIdx.x) {                  // this block's 8 threads write
#pragma unroll
        for (int j = 0; j < 8; j++) {
            int g = lab[j];
            int rank = 0;
#pragma unroll
            for (int j2 = 0; j2 < 8; j2++)
                if (j2 < j) rank += (lab[j2] == g);
            g_perm[baseS[g] + (int)h[g][t] + rank] = t * 8 + j;
        }
    }
}

// ---------------------------------------------------------------------------
// Kernel 2: FC1 GEMM: 64x128 tile, BK=32, 256 thr, occ 2. (R8, unchanged)
// ---------------------------------------------------------------------------
__global__ __launch_bounds__(256, 2) void fc1_kernel(const float* __restrict__ x,
                                                     const float* __restrict__ tab) {
    const int tile = blockIdx.y;
    const int rows = g_tileRows[tile];
    if (rows == 0) return;
    const int grp   = g_tileGroup[tile];
    const int start = g_tileStart[tile];
    const int n0    = blockIdx.x * 128;
    const float* W  = tab + (size_t)grp * ((IN_DIM + 1) * HIDDEN);

    __shared__ __align__(16) __nv_bfloat16 As[2][64][40];
    __shared__ __align__(16) __nv_bfloat16 Bs[2][32][136];
    __shared__ int rowIdx[64];

    const int t = threadIdx.x, lane = t & 31, warp = t >> 5;
    const int wm = warp >> 2, wn = warp & 3;

    if (t < 64) rowIdx[t] = (t < rows) ? g_perm[start + t] : -1;
    __syncthreads();

    int ar[2], ac4[2], alim[2]; const float* aptr[2];
#pragma unroll
    for (int p = 0; p < 2; p++) {
        int idx = t + p * 256;
        ar[p] = idx >> 3; ac4[p] = idx & 7;
        int gr = rowIdx[ar[p]];
        aptr[p] = x + (size_t)max(gr, 0) * IN_DIM + ac4[p] * 4;
        alim[p] = (gr >= 0) ? (IN_DIM - ac4[p] * 4) : 0;
    }
    int br[4], bc4[4];
#pragma unroll
    for (int p = 0; p < 4; p++) { int idx = t + p * 256; br[p] = idx >> 5; bc4[p] = idx & 31; }

    float acc[2][4][4];
#pragma unroll
    for (int mi = 0; mi < 2; mi++)
#pragma unroll
        for (int ni = 0; ni < 4; ni++)
#pragma unroll
            for (int j = 0; j < 4; j++) acc[mi][ni][j] = 0.f;

    const float4 Z4 = make_float4(0.f, 0.f, 0.f, 0.f);
    float4 aL[2], bL[4];
#pragma unroll
    for (int p = 0; p < 2; p++)
        aL[p] = (alim[p] > 0) ? *(const float4*)(aptr[p]) : Z4;
#pragma unroll
    for (int p = 0; p < 4; p++)
        bL[p] = *(const float4*)&W[(size_t)br[p] * HIDDEN + n0 + bc4[p] * 4];
#pragma unroll
    for (int p = 0; p < 2; p++) {
        *(uint32_t*)&As[0][ar[p]][ac4[p] * 4]     = f2bf2(aL[p].x, aL[p].y);
        *(uint32_t*)&As[0][ar[p]][ac4[p] * 4 + 2] = f2bf2(aL[p].z, aL[p].w);
    }
#pragma unroll
    for (int p = 0; p < 4; p++) {
        *(uint32_t*)&Bs[0][br[p]][bc4[p] * 4]     = f2bf2(bL[p].x, bL[p].y);
        *(uint32_t*)&Bs[0][br[p]][bc4[p] * 4 + 2] = f2bf2(bL[p].z, bL[p].w);
    }
    __syncthreads();

    const int NIT = (IN_DIM + 31) / 32;    // 25
    for (int it = 0; it < NIT; ++it) {
        const int cur = it & 1;
        if (it + 1 < NIT) {
            const int k0 = (it + 1) * 32;
#pragma unroll
            for (int p = 0; p < 2; p++)
                aL[p] = (k0 < alim[p]) ? *(const float4*)(aptr[p] + k0) : Z4;
#pragma unroll
            for (int p = 0; p < 4; p++) {
                int kr = k0 + br[p];
                const float4 v = *(const float4*)&W[(size_t)min(kr, IN_DIM) * HIDDEN + n0 + bc4[p] * 4];
                bL[p] = (kr < IN_DIM) ? v : Z4;
            }
        }

        uint32_t a[2][2][4], b[2][4][2];
#pragma unroll
        for (int mi = 0; mi < 2; mi++)
#pragma unroll
            for (int kh = 0; kh < 2; kh++) {
                uint32_t sa = (uint32_t)__cvta_generic_to_shared(
                    &As[cur][wm * 32 + mi * 16 + (lane & 15)][kh * 16 + (lane >> 4) * 8]);
                ldsm_x4(a[mi][kh][0], a[mi][kh][1], a[mi][kh][2], a[mi][kh][3], sa);
            }
#pragma unroll
        for (int kh = 0; kh < 2; kh++)
#pragma unroll
            for (int half = 0; half < 2; half++) {
                uint32_t sb = (uint32_t)__cvta_generic_to_shared(
                    &Bs[cur][kh * 16 + (lane & 7) + ((lane >> 3) & 1) * 8]
                       [wn * 32 + half * 16 + (lane >> 4) * 8]);
                ldsm_x4_t(b[kh][2 * half][0], b[kh][2 * half][1],
                          b[kh][2 * half + 1][0], b[kh][2 * half + 1][1], sb);
            }
#pragma unroll
        for (int kh = 0; kh < 2; kh++)
#pragma unroll
            for (int mi = 0; mi < 2; mi++)
#pragma unroll
                for (int ni = 0; ni < 4; ni++)
                    mma16816_c(acc[mi][ni], a[mi][kh], b[kh][ni]);

        if (it + 1 < NIT) {
            const int nxt = cur ^ 1;
#pragma unroll
            for (int p = 0; p < 2; p++) {
                *(uint32_t*)&As[nxt][ar[p]][ac4[p] * 4]     = f2bf2(aL[p].x, aL[p].y);
                *(uint32_t*)&As[nxt][ar[p]][ac4[p] * 4 + 2] = f2bf2(aL[p].z, aL[p].w);
            }
#pragma unroll
            for (int p = 0; p < 4; p++) {
                *(uint32_t*)&Bs[nxt][br[p]][bc4[p] * 4]     = f2bf2(bL[p].x, bL[p].y);
                *(uint32_t*)&Bs[nxt][br[p]][bc4[p] * 4 + 2] = f2bf2(bL[p].z, bL[p].w);
            }
        }
        __syncthreads();
    }

    const float* bias = W + (size_t)IN_DIM * HIDDEN + n0;
    uint32_t* h1u = (uint32_t*)g_h1;
#pragma unroll
    for (int ni = 0; ni < 4; ni++) {
        int c = wn * 32 + ni * 8 + (lane & 3) * 2;
        float2 bb = *(const float2*)&bias[c];
#pragma unroll
        for (int mi = 0; mi < 2; mi++) {
            int r0 = wm * 32 + mi * 16 + (lane >> 2);
            if (r0 < rows) {
                float vx = fmaxf(acc[mi][ni][0] + bb.x, 0.f);
                float vy = fmaxf(acc[mi][ni][1] + bb.y, 0.f);
                h1u[((size_t)(start + r0) * HIDDEN + n0 + c) >> 1] = f2bf2(vx, vy);
            }
            int r1 = r0 + 8;
            if (r1 < rows) {
                float vx = fmaxf(acc[mi][ni][2] + bb.x, 0.f);
                float vy = fmaxf(acc[mi][ni][3] + bb.y, 0.f);
                h1u[((size_t)(start + r1) * HIDDEN + n0 + c) >> 1] = f2bf2(vx, vy);
            }
        }
    }
}

// ---------------------------------------------------------------------------
// Kernel 3: FC2 split-K partial + FLAT fused combine tail.
// grid (42, 4) = 168 blocks (single wave at occ 2 -> spin is deadlock-free).
// Every block (including empty-tile blocks) arrives on g_done after a
// threadfence; all blocks then spin to 168 and each executes a flat 1/168
// slice of the combine (bias + sigmoid + scatter), reading partials __ldcg.
// Fixed k-order summation -> deterministic output values.
// ---------------------------------------------------------------------------
__global__ __launch_bounds__(256, 2) void fc2p_kernel(const int*   __restrict__ m,
                                                      const float* __restrict__ tab,
                                                      float*       __restrict__ out) {
    const int tile = blockIdx.x;
    const int kc   = blockIdx.y;
    const int rows = g_tileRows[tile];
    const int t = threadIdx.x, lane = t & 31, warp = t >> 5;
    const int wm = warp >> 2, wn = warp & 3;

    __shared__ __align__(16) __nv_bfloat16 As[64][136];
    __shared__ __align__(16) __nv_bfloat16 Bs[64][136];

    if (rows > 0) {
        const int grp   = g_tileGroup[tile];
        const int start = g_tileStart[tile];
        const float* W  = tab + (size_t)grp * ((HIDDEN + 1) * STYLE) + (size_t)(kc * 128) * STYLE;

        {
            const __nv_bfloat16* h1 = g_h1 + (size_t)start * HIDDEN + kc * 128;
#pragma unroll
            for (int p = 0; p < 2; p++) {
                int idx = t + p * 256;
                int r = idx >> 3, q = idx & 7;
                *(uint4*)&As[r][q * 8] = *(const uint4*)(h1 + (size_t)r * HIDDEN + q * 8);
            }
        }

        float acc[2][4][4];
#pragma unroll
        for (int mi = 0; mi < 2; mi++)
#pragma unroll
            for (int ni = 0; ni < 4; ni++)
#pragma unroll
                for (int j = 0; j < 4; j++) acc[mi][ni][j] = 0.f;

#pragma unroll
        for (int h2 = 0; h2 < 2; h2++) {
#pragma unroll
            for (int p = 0; p < 8; p++) {
                int idx = t + p * 256;
                int r = idx >> 5, c4 = idx & 31;
                float4 v = *(const float4*)&W[(size_t)(h2 * 64 + r) * STYLE + c4 * 4];
                *(uint32_t*)&Bs[r][c4 * 4]     = f2bf2(v.x, v.y);
                *(uint32_t*)&Bs[r][c4 * 4 + 2] = f2bf2(v.z, v.w);
            }
            __syncthreads();

#pragma unroll
            for (int kh = 0; kh < 4; kh++) {
                uint32_t a[2][4], b[4][2];
#pragma unroll
                for (int mi = 0; mi < 2; mi++) {
                    uint32_t sa = (uint32_t)__cvta_generic_to_shared(
                        &As[wm * 32 + mi * 16 + (lane & 15)][h2 * 64 + kh * 16 + (lane >> 4) * 8]);
                    ldsm_x4(a[mi][0], a[mi][1], a[mi][2], a[mi][3], sa);
                }
#pragma unroll
                for (int half = 0; half < 2; half++) {
                    uint32_t sb = (uint32_t)__cvta_generic_to_shared(
                        &Bs[kh * 16 + (lane & 7) + ((lane >> 3) & 1) * 8]
                           [wn * 32 + half * 16 + (lane >> 4) * 8]);
                    ldsm_x4_t(b[2 * half][0], b[2 * half][1], b[2 * half + 1][0], b[2 * half + 1][1], sb);
                }
#pragma unroll
                for (int mi = 0; mi < 2; mi++)
#pragma unroll
                    for (int ni = 0; ni < 4; ni++)
                        mma16816_c(acc[mi][ni], a[mi], b[ni]);
            }
            __syncthreads();
        }

        __nv_bfloat16* P = g_part + (size_t)kc * BATCH * STYLE;
#pragma unroll
        for (int ni = 0; ni < 4; ni++) {
            int c = wn * 32 + ni * 8 + (lane & 3) * 2;
#pragma unroll
            for (int mi = 0; mi < 2; mi++) {
                int r0 = wm * 32 + mi * 16 + (lane >> 2);
                if (r0 < rows)
                    *(uint32_t*)&P[(size_t)(start + r0) * STYLE + c] =
                        f2bf2(acc[mi][ni][0], acc[mi][ni][1]);
                int r1 = r0 + 8;
                if (r1 < rows)
                    *(uint32_t*)&P[(size_t)(start + r1) * STYLE + c] =
                        f2bf2(acc[mi][ni][2], acc[mi][ni][3]);
            }
        }
    }

    // ---- arrive (threadFenceReduction pattern), then spin to full count ----
    __threadfence();                     // every thread fences its own stores
    __syncthreads();                     // fences complete before arrival
    if (t == 0) atomicAdd(&g_done, 1);
    if (t == 0) {
        while (atomicAdd(&g_done, 0) < FC2_BLOCKS) __nanosleep(32);
    }
    __syncthreads();

    // ---- flat combine slice: 1/168 of 65,536 float4 items ------------------
    const int blk = blockIdx.y * MAX_TILES + blockIdx.x;        // 0..167
    const int NITEMS = BATCH * 32;
    const int per = (NITEMS + FC2_BLOCKS - 1) / FC2_BLOCKS;     // 391
    const int lo = blk * per;
    const int hi = min(lo + per, NITEMS);

    for (int i = lo + t; i < hi; i += 256) {
        const int pos = i >> 5;                                 // permuted row
        const int c4  = i & 31;                                 // float4 column
        const int orow = g_perm[pos];                           // warp-broadcast
        const int grp2 = m[orow];
        const float* bias = tab + (size_t)grp2 * ((HIDDEN + 1) * STYLE)
                          + (size_t)HIDDEN * STYLE;
        float4 bb = *(const float4*)&bias[c4 * 4];

        const size_t off = (size_t)pos * STYLE + c4 * 4;        // bf16 index
        float s0 = 0.f, s1 = 0.f, s2 = 0.f, s3 = 0.f;
#pragma unroll
        for (int k = 0; k < KSPLIT; k++) {
            uint2 vv = __ldcg((const uint2*)(g_part + (size_t)k * BATCH * STYLE + off));
            float2 f0 = __bfloat1622float2(*(const __nv_bfloat162*)&vv.x);
            float2 f1 = __bfloat1622float2(*(const __nv_bfloat162*)&vv.y);
            s0 += f0.x; s1 += f0.y; s2 += f1.x; s3 += f1.y;
        }
        float4 v;
        v.x = 1.f / (1.f + __expf(-(s0 + bb.x)));
        v.y = 1.f / (1.f + __expf(-(s1 + bb.y)));
        v.z = 1.f / (1.f + __expf(-(s2 + bb.z)));
        v.w = 1.f / (1.f + __expf(-(s3 + bb.w)));
        *(float4*)&out[(size_t)orow * STYLE + c4 * 4] = v;
    }
}

extern "C" void kernel_launch(void* const* d_in, const int* in_sizes, int n_in,
                              void* d_out, int out_size) {
    const float* x         = (const float*)d_in[0];
    const int*   m         = (const int*)d_in[1];
    const float* fc1_table = (const float*)d_in[2];
    const float* fc2_table = (const float*)d_in[3];
    float*       out       = (float*)d_out;

    group_kernel<<<32, 256>>>(m);
    fc1_kernel<<<dim3(HIDDEN / 128, MAX_TILES), 256>>>(x, fc1_table);
    fc2p_kernel<<<dim3(MAX_TILES, KSPLIT), 256>>>(m, fc2_table, out);
}

// round 14
// speedup vs baseline: 1.5801x; 1.0021x over previous
#include <cuda_runtime.h>
#include <cuda_bf16.h>
#include <math.h>
#include <stdint.h>

#define IN_DIM   784
#define HIDDEN   512
#define STYLE    128
#define BATCH    2048
#define NUM_LABELS 10

#define BM 64
#define MAX_TILES (BATCH / BM + NUM_LABELS)   // 42

// Scratch (no allocations allowed -> __device__ globals)
__device__ int   g_perm[BATCH];
__device__ int   g_tileGroup[MAX_TILES];
__device__ int   g_tileStart[MAX_TILES];
__device__ int   g_tileRows[MAX_TILES];
__device__ __nv_bfloat16 g_h1[(BATCH + 128) * HIDDEN];           // padded

// ---------------------------------------------------------------------------
// Helpers
// ---------------------------------------------------------------------------
__device__ __forceinline__ uint32_t f2bf2(float lo, float hi) {
    __nv_bfloat162 h = __floats2bfloat162_rn(lo, hi);
    return *reinterpret_cast<uint32_t*>(&h);
}

__device__ __forceinline__ void ldsm_x4(uint32_t& r0, uint32_t& r1, uint32_t& r2, uint32_t& r3,
                                        uint32_t saddr) {
    asm volatile("ldmatrix.sync.aligned.m8n8.x4.shared.b16 {%0,%1,%2,%3}, [%4];"
                 : "=r"(r0), "=r"(r1), "=r"(r2), "=r"(r3) : "r"(saddr));
}

__device__ __forceinline__ void ldsm_x4_t(uint32_t& r0, uint32_t& r1, uint32_t& r2, uint32_t& r3,
                                          uint32_t saddr) {
    asm volatile("ldmatrix.sync.aligned.m8n8.x4.trans.shared.b16 {%0,%1,%2,%3}, [%4];"
                 : "=r"(r0), "=r"(r1), "=r"(r2), "=r"(r3) : "r"(saddr));
}

__device__ __forceinline__ void mma16816_c(float* c, const uint32_t* a, const uint32_t* b) {
    asm volatile("mma.sync.aligned.m16n8k16.row.col.f32.bf16.bf16.f32 "
                 "{%0,%1,%2,%3}, {%4,%5,%6,%7}, {%8,%9}, {%0,%1,%2,%3};"
                 : "+f"(c[0]), "+f"(c[1]), "+f"(c[2]), "+f"(c[3])
                 : "r"(a[0]), "r"(a[1]), "r"(a[2]), "r"(a[3]), "r"(b[0]), "r"(b[1]));
}

// ---------------------------------------------------------------------------
// Kernel 1: grouping, 32 blocks (R8 winner, unchanged).
// ---------------------------------------------------------------------------
__global__ void group_kernel(const int* __restrict__ m) {
    __shared__ uint16_t h[NUM_LABELS][257];
    __shared__ int cnt[NUM_LABELS];
    __shared__ int baseS[NUM_LABELS];
    const int t = threadIdx.x, lane = t & 31, warp = t >> 5;

    int4 lv0 = ((const int4*)m)[t * 2];
    int4 lv1 = ((const int4*)m)[t * 2 + 1];
    int lab[8] = {lv0.x, lv0.y, lv0.z, lv0.w, lv1.x, lv1.y, lv1.z, lv1.w};

#pragma unroll
    for (int g = 0; g < NUM_LABELS; g++) {
        int c = 0;
#pragma unroll
        for (int j = 0; j < 8; j++) c += (lab[j] == g);
        h[g][t] = (uint16_t)c;
    }
    __syncthreads();

    for (int g = warp; g < NUM_LABELS; g += 8) {
        int s = 0;
#pragma unroll
        for (int j = 0; j < 8; j++) s += h[g][lane * 8 + j];
        int incl = s;
#pragma unroll
        for (int d = 1; d < 32; d <<= 1) {
            int v = __shfl_up_sync(0xffffffffu, incl, d);
            if (lane >= d) incl += v;
        }
        int run = incl - s;
#pragma unroll
        for (int j = 0; j < 8; j++) {
            int tt = lane * 8 + j;
            int v = h[g][tt];
            h[g][tt] = (uint16_t)run;
            run += v;
        }
        if (lane == 31) cnt[g] = run;
    }
    __syncthreads();

    if (t == 0) {
        int o = 0;
        for (int g = 0; g < NUM_LABELS; g++) { baseS[g] = o; o += cnt[g]; }
        if (blockIdx.x == 0) {                          // tile table
            int tile = 0;
            for (int g = 0; g < NUM_LABELS; g++) {
                int c = cnt[g], nt = (c + BM - 1) / BM;
                for (int j = 0; j < nt; j++) {
                    g_tileGroup[tile] = g;
                    g_tileStart[tile] = baseS[g] + j * BM;
                    g_tileRows[tile]  = min(BM, c - j * BM);
                    tile++;
                }
            }
            for (; tile < MAX_TILES; tile++) g_tileRows[tile] = 0;
        }
    }
    __syncthreads();

    if ((t >> 3) == (int)blockIdx.x) {                  // this block's 8 threads write
#pragma unroll
        for (int j = 0; j < 8; j++) {
            int g = lab[j];
            int rank = 0;
#pragma unroll
            for (int j2 = 0; j2 < 8; j2++)
                if (j2 < j) rank += (lab[j2] == g);
            g_perm[baseS[g] + (int)h[g][t] + rank] = t * 8 + j;
        }
    }
}

// ---------------------------------------------------------------------------
// Kernel 2: FC1 GEMM: 64x128 tile, BK=32, 256 thr, occ 2. (R8, unchanged)
// ---------------------------------------------------------------------------
__global__ __launch_bounds__(256, 2) void fc1_kernel(const float* __restrict__ x,
                                                     const float* __restrict__ tab) {
    const int tile = blockIdx.y;
    const int rows = g_tileRows[tile];
    if (rows == 0) return;
    const int grp   = g_tileGroup[tile];
    const int start = g_tileStart[tile];
    const int n0    = blockIdx.x * 128;
    const float* W  = tab + (size_t)grp * ((IN_DIM + 1) * HIDDEN);

    __shared__ __align__(16) __nv_bfloat16 As[2][64][40];
    __shared__ __align__(16) __nv_bfloat16 Bs[2][32][136];
    __shared__ int rowIdx[64];

    const int t = threadIdx.x, lane = t & 31, warp = t >> 5;
    const int wm = warp >> 2, wn = warp & 3;

    if (t < 64) rowIdx[t] = (t < rows) ? g_perm[start + t] : -1;
    __syncthreads();

    int ar[2], ac4[2], alim[2]; const float* aptr[2];
#pragma unroll
    for (int p = 0; p < 2; p++) {
        int idx = t + p * 256;
        ar[p] = idx >> 3; ac4[p] = idx & 7;
        int gr = rowIdx[ar[p]];
        aptr[p] = x + (size_t)max(gr, 0) * IN_DIM + ac4[p] * 4;
        alim[p] = (gr >= 0) ? (IN_DIM - ac4[p] * 4) : 0;
    }
    int br[4], bc4[4];
#pragma unroll
    for (int p = 0; p < 4; p++) { int idx = t + p * 256; br[p] = idx >> 5; bc4[p] = idx & 31; }

    float acc[2][4][4];
#pragma unroll
    for (int mi = 0; mi < 2; mi++)
#pragma unroll
        for (int ni = 0; ni < 4; ni++)
#pragma unroll
            for (int j = 0; j < 4; j++) acc[mi][ni][j] = 0.f;

    const float4 Z4 = make_float4(0.f, 0.f, 0.f, 0.f);
    float4 aL[2], bL[4];
#pragma unroll
    for (int p = 0; p < 2; p++)
        aL[p] = (alim[p] > 0) ? *(const float4*)(aptr[p]) : Z4;
#pragma unroll
    for (int p = 0; p < 4; p++)
        bL[p] = *(const float4*)&W[(size_t)br[p] * HIDDEN + n0 + bc4[p] * 4];
#pragma unroll
    for (int p = 0; p < 2; p++) {
        *(uint32_t*)&As[0][ar[p]][ac4[p] * 4]     = f2bf2(aL[p].x, aL[p].y);
        *(uint32_t*)&As[0][ar[p]][ac4[p] * 4 + 2] = f2bf2(aL[p].z, aL[p].w);
    }
#pragma unroll
    for (int p = 0; p < 4; p++) {
        *(uint32_t*)&Bs[0][br[p]][bc4[p] * 4]     = f2bf2(bL[p].x, bL[p].y);
        *(uint32_t*)&Bs[0][br[p]][bc4[p] * 4 + 2] = f2bf2(bL[p].z, bL[p].w);
    }
    __syncthreads();

    const int NIT = (IN_DIM + 31) / 32;    // 25
    for (int it = 0; it < NIT; ++it) {
        const int cur = it & 1;
        if (it + 1 < NIT) {
            const int k0 = (it + 1) * 32;
#pragma unroll
            for (int p = 0; p < 2; p++)
                aL[p] = (k0 < alim[p]) ? *(const float4*)(aptr[p] + k0) : Z4;
#pragma unroll
            for (int p = 0; p < 4; p++) {
                int kr = k0 + br[p];
                const float4 v = *(const float4*)&W[(size_t)min(kr, IN_DIM) * HIDDEN + n0 + bc4[p] * 4];
                bL[p] = (kr < IN_DIM) ? v : Z4;
            }
        }

        uint32_t a[2][2][4], b[2][4][2];
#pragma unroll
        for (int mi = 0; mi < 2; mi++)
#pragma unroll
            for (int kh = 0; kh < 2; kh++) {
                uint32_t sa = (uint32_t)__cvta_generic_to_shared(
                    &As[cur][wm * 32 + mi * 16 + (lane & 15)][kh * 16 + (lane >> 4) * 8]);
                ldsm_x4(a[mi][kh][0], a[mi][kh][1], a[mi][kh][2], a[mi][kh][3], sa);
            }
#pragma unroll
        for (int kh = 0; kh < 2; kh++)
#pragma unroll
            for (int half = 0; half < 2; half++) {
                uint32_t sb = (uint32_t)__cvta_generic_to_shared(
                    &Bs[cur][kh * 16 + (lane & 7) + ((lane >> 3) & 1) * 8]
                       [wn * 32 + half * 16 + (lane >> 4) * 8]);
                ldsm_x4_t(b[kh][2 * half][0], b[kh][2 * half][1],
                          b[kh][2 * half + 1][0], b[kh][2 * half + 1][1], sb);
            }
#pragma unroll
        for (int kh = 0; kh < 2; kh++)
#pragma unroll
            for (int mi = 0; mi < 2; mi++)
#pragma unroll
                for (int ni = 0; ni < 4; ni++)
                    mma16816_c(acc[mi][ni], a[mi][kh], b[kh][ni]);

        if (it + 1 < NIT) {
            const int nxt = cur ^ 1;
#pragma unroll
            for (int p = 0; p < 2; p++) {
                *(uint32_t*)&As[nxt][ar[p]][ac4[p] * 4]     = f2bf2(aL[p].x, aL[p].y);
                *(uint32_t*)&As[nxt][ar[p]][ac4[p] * 4 + 2] = f2bf2(aL[p].z, aL[p].w);
            }
#pragma unroll
            for (int p = 0; p < 4; p++) {
                *(uint32_t*)&Bs[nxt][br[p]][bc4[p] * 4]     = f2bf2(bL[p].x, bL[p].y);
                *(uint32_t*)&Bs[nxt][br[p]][bc4[p] * 4 + 2] = f2bf2(bL[p].z, bL[p].w);
            }
        }
        __syncthreads();
    }

    const float* bias = W + (size_t)IN_DIM * HIDDEN + n0;
    uint32_t* h1u = (uint32_t*)g_h1;
#pragma unroll
    for (int ni = 0; ni < 4; ni++) {
        int c = wn * 32 + ni * 8 + (lane & 3) * 2;
        float2 bb = *(const float2*)&bias[c];
#pragma unroll
        for (int mi = 0; mi < 2; mi++) {
            int r0 = wm * 32 + mi * 16 + (lane >> 2);
            if (r0 < rows) {
                float vx = fmaxf(acc[mi][ni][0] + bb.x, 0.f);
                float vy = fmaxf(acc[mi][ni][1] + bb.y, 0.f);
                h1u[((size_t)(start + r0) * HIDDEN + n0 + c) >> 1] = f2bf2(vx, vy);
            }
            int r1 = r0 + 8;
            if (r1 < rows) {
                float vx = fmaxf(acc[mi][ni][2] + bb.x, 0.f);
                float vy = fmaxf(acc[mi][ni][3] + bb.y, 0.f);
                h1u[((size_t)(start + r1) * HIDDEN + n0 + c) >> 1] = f2bf2(vx, vy);
            }
        }
    }
}

// ---------------------------------------------------------------------------
// Kernel 3: FC2 GEMM, N-split (NO split-K, NO combine). grid (42, 2).
// Each block: 64 rows x 64 cols, full K=512 in 8 BK=64 phases with
// register-staged double buffering (one __syncthreads per phase).
// Epilogue: +bias, sigmoid, scatter via g_perm directly to out.
// ---------------------------------------------------------------------------
__global__ __launch_bounds__(256, 2) void fc2_kernel(const float* __restrict__ tab,
                                                     float* __restrict__ out) {
    const int tile = blockIdx.x;
    const int nh   = blockIdx.y;                        // 0 or 1: column half
    const int rows = g_tileRows[tile];
    if (rows == 0) return;
    const int grp   = g_tileGroup[tile];
    const int start = g_tileStart[tile];
    const float* W  = tab + (size_t)grp * ((HIDDEN + 1) * STYLE) + nh * 64;

    __shared__ __align__(16) __nv_bfloat16 As[2][64][72];   // 64 + 8 pad, 9.2 KB
    __shared__ __align__(16) __nv_bfloat16 Bs[2][64][72];
    __shared__ int rowIdx[64];

    const int t = threadIdx.x, lane = t & 31, warp = t >> 5;
    const int wm = warp >> 2, wn = warp & 3;            // 2 x 4 warps -> 32x16 warp tile

    if (t < 64) rowIdx[t] = (t < rows) ? g_perm[start + t] : 0;
    __syncthreads();

    // A: 64 rows x 64 bf16 per phase = 512 uint4, 2/thread
    int ar[2], aq[2];
#pragma unroll
    for (int p = 0; p < 2; p++) { int idx = t + p * 256; ar[p] = idx >> 3; aq[p] = idx & 7; }
    const __nv_bfloat16* h1b = g_h1 + (size_t)start * HIDDEN;
    // B: 64 k-rows x 16 float4 per phase = 1024, 4/thread
    int br[4], bc4[4];
#pragma unroll
    for (int p = 0; p < 4; p++) { int idx = t + p * 256; br[p] = idx >> 4; bc4[p] = idx & 15; }

    float acc[2][2][4];
#pragma unroll
    for (int mi = 0; mi < 2; mi++)
#pragma unroll
        for (int ni = 0; ni < 2; ni++)
#pragma unroll
            for (int j = 0; j < 4; j++) acc[mi][ni][j] = 0.f;

    uint4 aL[2]; float4 bL[4];
    // Prologue: phase 0
#pragma unroll
    for (int p = 0; p < 2; p++)
        aL[p] = *(const uint4*)(h1b + (size_t)ar[p] * HIDDEN + aq[p] * 8);
#pragma unroll
    for (int p = 0; p < 4; p++)
        bL[p] = *(const float4*)&W[(size_t)br[p] * STYLE + bc4[p] * 4];
#pragma unroll
    for (int p = 0; p < 2; p++)
        *(uint4*)&As[0][ar[p]][aq[p] * 8] = aL[p];
#pragma unroll
    for (int p = 0; p < 4; p++) {
        *(uint32_t*)&Bs[0][br[p]][bc4[p] * 4]     = f2bf2(bL[p].x, bL[p].y);
        *(uint32_t*)&Bs[0][br[p]][bc4[p] * 4 + 2] = f2bf2(bL[p].z, bL[p].w);
    }
    __syncthreads();

    const int NPH = HIDDEN / 64;                        // 8
    for (int ph = 0; ph < NPH; ++ph) {
        const int cur = ph & 1;
        if (ph + 1 < NPH) {
            const int k0 = (ph + 1) * 64;
#pragma unroll
            for (int p = 0; p < 2; p++)
                aL[p] = *(const uint4*)(h1b + (size_t)ar[p] * HIDDEN + k0 + aq[p] * 8);
#pragma unroll
            for (int p = 0; p < 4; p++)
                bL[p] = *(const float4*)&W[(size_t)(k0 + br[p]) * STYLE + bc4[p] * 4];
        }

#pragma unroll
        for (int kh = 0; kh < 4; kh++) {
            uint32_t a[2][4], b[2][2];
#pragma unroll
            for (int mi = 0; mi < 2; mi++) {
                uint32_t sa = (uint32_t)__cvta_generic_to_shared(
                    &As[cur][wm * 32 + mi * 16 + (lane & 15)][kh * 16 + (lane >> 4) * 8]);
                ldsm_x4(a[mi][0], a[mi][1], a[mi][2], a[mi][3], sa);
            }
            uint32_t sb = (uint32_t)__cvta_generic_to_shared(
                &Bs[cur][kh * 16 + (lane & 7) + ((lane >> 3) & 1) * 8]
                   [wn * 16 + (lane >> 4) * 8]);
            ldsm_x4_t(b[0][0], b[0][1], b[1][0], b[1][1], sb);
#pragma unroll
            for (int mi = 0; mi < 2; mi++)
#pragma unroll
                for (int ni = 0; ni < 2; ni++)
                    mma16816_c(acc[mi][ni], a[mi], b[ni]);
        }

        if (ph + 1 < NPH) {
            const int nxt = cur ^ 1;
#pragma unroll
            for (int p = 0; p < 2; p++)
                *(uint4*)&As[nxt][ar[p]][aq[p] * 8] = aL[p];
#pragma unroll
            for (int p = 0; p < 4; p++) {
                *(uint32_t*)&Bs[nxt][br[p]][bc4[p] * 4]     = f2bf2(bL[p].x, bL[p].y);
                *(uint32_t*)&Bs[nxt][br[p]][bc4[p] * 4 + 2] = f2bf2(bL[p].z, bL[p].w);
            }
        }
        __syncthreads();
    }

    // Epilogue: +bias, sigmoid, scatter fp32
    const float* bias = tab + (size_t)grp * ((HIDDEN + 1) * STYLE)
                      + (size_t)HIDDEN * STYLE + nh * 64;
#pragma unroll
    for (int ni = 0; ni < 2; ni++) {
        int c = wn * 16 + ni * 8 + (lane & 3) * 2;
        float2 bb = *(const float2*)&bias[c];
#pragma unroll
        for (int mi = 0; mi < 2; mi++) {
            int r0 = wm * 32 + mi * 16 + (lane >> 2);
            if (r0 < rows) {
                int orow = rowIdx[r0];
                float2 v;
                v.x = 1.f / (1.f + __expf(-(acc[mi][ni][0] + bb.x)));
                v.y = 1.f / (1.f + __expf(-(acc[mi][ni][1] + bb.y)));
                *(float2*)&out[(size_t)orow * STYLE + nh * 64 + c] = v;
            }
            int r1 = r0 + 8;
            if (r1 < rows) {
                int orow = rowIdx[r1];
                float2 v;
                v.x = 1.f / (1.f + __expf(-(acc[mi][ni][2] + bb.x)));
                v.y = 1.f / (1.f + __expf(-(acc[mi][ni][3] + bb.y)));
                *(float2*)&out[(size_t)orow * STYLE + nh * 64 + c] = v;
            }
        }
    }
}

extern "C" void kernel_launch(void* const* d_in, const int* in_sizes, int n_in,
                              void* d_out, int out_size) {
    const float* x         = (const float*)d_in[0];
    const int*   m         = (const int*)d_in[1];
    const float* fc1_table = (const float*)d_in[2];
    const float* fc2_table = (const float*)d_in[3];
    float*       out       = (float*)d_out;

    group_kernel<<<32, 256>>>(m);
    fc1_kernel<<<dim3(HIDDEN / 128, MAX_TILES), 256>>>(x, fc1_table);
    fc2_kernel<<<dim3(MAX_TILES, 2), 256>>>(fc2_table, out);
}

// round 15
// speedup vs baseline: 1.6875x; 1.0680x over previous
#include <cuda_runtime.h>
#include <cuda_bf16.h>
#include <math.h>
#include <stdint.h>

#define IN_DIM   784
#define HIDDEN   512
#define STYLE    128
#define BATCH    2048
#define NUM_LABELS 10

#define BM 64
#define MAX_TILES (BATCH / BM + NUM_LABELS)   // 42

// Scratch (no allocations allowed -> __device__ globals)
__device__ int   g_perm[BATCH];
__device__ int   g_tileGroup[MAX_TILES];
__device__ int   g_tileStart[MAX_TILES];
__device__ int   g_tileRows[MAX_TILES];
__device__ __nv_bfloat16 g_h1[(BATCH + 128) * HIDDEN];           // padded

// ---------------------------------------------------------------------------
// Helpers
// ---------------------------------------------------------------------------
__device__ __forceinline__ uint32_t f2bf2(float lo, float hi) {
    __nv_bfloat162 h = __floats2bfloat162_rn(lo, hi);
    return *reinterpret_cast<uint32_t*>(&h);
}

__device__ __forceinline__ void ldsm_x4(uint32_t& r0, uint32_t& r1, uint32_t& r2, uint32_t& r3,
                                        uint32_t saddr) {
    asm volatile("ldmatrix.sync.aligned.m8n8.x4.shared.b16 {%0,%1,%2,%3}, [%4];"
                 : "=r"(r0), "=r"(r1), "=r"(r2), "=r"(r3) : "r"(saddr));
}

__device__ __forceinline__ void ldsm_x4_t(uint32_t& r0, uint32_t& r1, uint32_t& r2, uint32_t& r3,
                                          uint32_t saddr) {
    asm volatile("ldmatrix.sync.aligned.m8n8.x4.trans.shared.b16 {%0,%1,%2,%3}, [%4];"
                 : "=r"(r0), "=r"(r1), "=r"(r2), "=r"(r3) : "r"(saddr));
}

__device__ __forceinline__ void mma16816_c(float* c, const uint32_t* a, const uint32_t* b) {
    asm volatile("mma.sync.aligned.m16n8k16.row.col.f32.bf16.bf16.f32 "
                 "{%0,%1,%2,%3}, {%4,%5,%6,%7}, {%8,%9}, {%0,%1,%2,%3};"
                 : "+f"(c[0]), "+f"(c[1]), "+f"(c[2]), "+f"(c[3])
                 : "r"(a[0]), "r"(a[1]), "r"(a[2]), "r"(a[3]), "r"(b[0]), "r"(b[1]));
}

// ---------------------------------------------------------------------------
// Kernel 1: grouping, 32 blocks. De-serialized: base & tile-count prefixes
// via warp-0 shfl scans (10 lanes), tile table filled by 42 threads in
// parallel. Stable counting sort -> deterministic.
// ---------------------------------------------------------------------------
__global__ void group_kernel(const int* __restrict__ m) {
    __shared__ uint16_t h[NUM_LABELS][257];
    __shared__ int cnt[NUM_LABELS];
    __shared__ int baseS[NUM_LABELS];
    __shared__ int ntBase[NUM_LABELS + 1];
    const int t = threadIdx.x, lane = t & 31, warp = t >> 5;

    int4 lv0 = ((const int4*)m)[t * 2];
    int4 lv1 = ((const int4*)m)[t * 2 + 1];
    int lab[8] = {lv0.x, lv0.y, lv0.z, lv0.w, lv1.x, lv1.y, lv1.z, lv1.w};

#pragma unroll
    for (int g = 0; g < NUM_LABELS; g++) {
        int c = 0;
#pragma unroll
        for (int j = 0; j < 8; j++) c += (lab[j] == g);
        h[g][t] = (uint16_t)c;
    }
    __syncthreads();

    for (int g = warp; g < NUM_LABELS; g += 8) {
        int s = 0;
#pragma unroll
        for (int j = 0; j < 8; j++) s += h[g][lane * 8 + j];
        int incl = s;
#pragma unroll
        for (int d = 1; d < 32; d <<= 1) {
            int v = __shfl_up_sync(0xffffffffu, incl, d);
            if (lane >= d) incl += v;
        }
        int run = incl - s;
#pragma unroll
        for (int j = 0; j < 8; j++) {
            int tt = lane * 8 + j;
            int v = h[g][tt];
            h[g][tt] = (uint16_t)run;
            run += v;
        }
        if (lane == 31) cnt[g] = run;
    }
    __syncthreads();

    // warp 0: parallel prefix over labels for base offsets AND tile counts
    if (warp == 0) {
        int c  = (lane < NUM_LABELS) ? cnt[lane] : 0;
        int inc = c;
#pragma unroll
        for (int d = 1; d < 32; d <<= 1) {
            int v = __shfl_up_sync(0xffffffffu, inc, d);
            if (lane >= d) inc += v;
        }
        if (lane < NUM_LABELS) baseS[lane] = inc - c;

        int nt  = (lane < NUM_LABELS) ? (c + BM - 1) >> 6 : 0;
        int incN = nt;
#pragma unroll
        for (int d = 1; d < 32; d <<= 1) {
            int v = __shfl_up_sync(0xffffffffu, incN, d);
            if (lane >= d) incN += v;
        }
        if (lane <= NUM_LABELS) ntBase[lane] = incN - nt;   // lane==10 -> total tiles
    }
    __syncthreads();

    // block 0: tile table filled by 42 threads in parallel
    if (blockIdx.x == 0 && t < MAX_TILES) {
        int total = ntBase[NUM_LABELS];
        if (t < total) {
            int g = 0;
#pragma unroll
            for (int gg = 1; gg < NUM_LABELS; gg++)
                if (t >= ntBase[gg]) g = gg;
            int j = t - ntBase[g];
            g_tileGroup[t] = g;
            g_tileStart[t] = baseS[g] + j * BM;
            g_tileRows[t]  = min(BM, cnt[g] - j * BM);
        } else {
            g_tileRows[t] = 0;
        }
    }

    if ((t >> 3) == (int)blockIdx.x) {                  // this block's 8 threads write
#pragma unroll
        for (int j = 0; j < 8; j++) {
            int g = lab[j];
            int rank = 0;
#pragma unroll
            for (int j2 = 0; j2 < 8; j2++)
                if (j2 < j) rank += (lab[j2] == g);
            g_perm[baseS[g] + (int)h[g][t] + rank] = t * 8 + j;
        }
    }
}

// ---------------------------------------------------------------------------
// Kernel 2: FC1 GEMM: 64x128 tile, BK=32, 256 thr, occ 2. (R8, unchanged)
// ---------------------------------------------------------------------------
__global__ __launch_bounds__(256, 2) void fc1_kernel(const float* __restrict__ x,
                                                     const float* __restrict__ tab) {
    const int tile = blockIdx.y;
    const int rows = g_tileRows[tile];
    if (rows == 0) return;
    const int grp   = g_tileGroup[tile];
    const int start = g_tileStart[tile];
    const int n0    = blockIdx.x * 128;
    const float* W  = tab + (size_t)grp * ((IN_DIM + 1) * HIDDEN);

    __shared__ __align__(16) __nv_bfloat16 As[2][64][40];
    __shared__ __align__(16) __nv_bfloat16 Bs[2][32][136];
    __shared__ int rowIdx[64];

    const int t = threadIdx.x, lane = t & 31, warp = t >> 5;
    const int wm = warp >> 2, wn = warp & 3;

    if (t < 64) rowIdx[t] = (t < rows) ? g_perm[start + t] : -1;
    __syncthreads();

    int ar[2], ac4[2], alim[2]; const float* aptr[2];
#pragma unroll
    for (int p = 0; p < 2; p++) {
        int idx = t + p * 256;
        ar[p] = idx >> 3; ac4[p] = idx & 7;
        int gr = rowIdx[ar[p]];
        aptr[p] = x + (size_t)max(gr, 0) * IN_DIM + ac4[p] * 4;
        alim[p] = (gr >= 0) ? (IN_DIM - ac4[p] * 4) : 0;
    }
    int br[4], bc4[4];
#pragma unroll
    for (int p = 0; p < 4; p++) { int idx = t + p * 256; br[p] = idx >> 5; bc4[p] = idx & 31; }

    float acc[2][4][4];
#pragma unroll
    for (int mi = 0; mi < 2; mi++)
#pragma unroll
        for (int ni = 0; ni < 4; ni++)
#pragma unroll
            for (int j = 0; j < 4; j++) acc[mi][ni][j] = 0.f;

    const float4 Z4 = make_float4(0.f, 0.f, 0.f, 0.f);
    float4 aL[2], bL[4];
#pragma unroll
    for (int p = 0; p < 2; p++)
        aL[p] = (alim[p] > 0) ? *(const float4*)(aptr[p]) : Z4;
#pragma unroll
    for (int p = 0; p < 4; p++)
        bL[p] = *(const float4*)&W[(size_t)br[p] * HIDDEN + n0 + bc4[p] * 4];
#pragma unroll
    for (int p = 0; p < 2; p++) {
        *(uint32_t*)&As[0][ar[p]][ac4[p] * 4]     = f2bf2(aL[p].x, aL[p].y);
        *(uint32_t*)&As[0][ar[p]][ac4[p] * 4 + 2] = f2bf2(aL[p].z, aL[p].w);
    }
#pragma unroll
    for (int p = 0; p < 4; p++) {
        *(uint32_t*)&Bs[0][br[p]][bc4[p] * 4]     = f2bf2(bL[p].x, bL[p].y);
        *(uint32_t*)&Bs[0][br[p]][bc4[p] * 4 + 2] = f2bf2(bL[p].z, bL[p].w);
    }
    __syncthreads();

    const int NIT = (IN_DIM + 31) / 32;    // 25
    for (int it = 0; it < NIT; ++it) {
        const int cur = it & 1;
        if (it + 1 < NIT) {
            const int k0 = (it + 1) * 32;
#pragma unroll
            for (int p = 0; p < 2; p++)
                aL[p] = (k0 < alim[p]) ? *(const float4*)(aptr[p] + k0) : Z4;
#pragma unroll
            for (int p = 0; p < 4; p++) {
                int kr = k0 + br[p];
                const float4 v = *(const float4*)&W[(size_t)min(kr, IN_DIM) * HIDDEN + n0 + bc4[p] * 4];
                bL[p] = (kr < IN_DIM) ? v : Z4;
            }
        }

        uint32_t a[2][2][4], b[2][4][2];
#pragma unroll
        for (int mi = 0; mi < 2; mi++)
#pragma unroll
            for (int kh = 0; kh < 2; kh++) {
                uint32_t sa = (uint32_t)__cvta_generic_to_shared(
                    &As[cur][wm * 32 + mi * 16 + (lane & 15)][kh * 16 + (lane >> 4) * 8]);
                ldsm_x4(a[mi][kh][0], a[mi][kh][1], a[mi][kh][2], a[mi][kh][3], sa);
            }
#pragma unroll
        for (int kh = 0; kh < 2; kh++)
#pragma unroll
            for (int half = 0; half < 2; half++) {
                uint32_t sb = (uint32_t)__cvta_generic_to_shared(
                    &Bs[cur][kh * 16 + (lane & 7) + ((lane >> 3) & 1) * 8]
                       [wn * 32 + half * 16 + (lane >> 4) * 8]);
                ldsm_x4_t(b[kh][2 * half][0], b[kh][2 * half][1],
                          b[kh][2 * half + 1][0], b[kh][2 * half + 1][1], sb);
            }
#pragma unroll
        for (int kh = 0; kh < 2; kh++)
#pragma unroll
            for (int mi = 0; mi < 2; mi++)
#pragma unroll
                for (int ni = 0; ni < 4; ni++)
                    mma16816_c(acc[mi][ni], a[mi][kh], b[kh][ni]);

        if (it + 1 < NIT) {
            const int nxt = cur ^ 1;
#pragma unroll
            for (int p = 0; p < 2; p++) {
                *(uint32_t*)&As[nxt][ar[p]][ac4[p] * 4]     = f2bf2(aL[p].x, aL[p].y);
                *(uint32_t*)&As[nxt][ar[p]][ac4[p] * 4 + 2] = f2bf2(aL[p].z, aL[p].w);
            }
#pragma unroll
            for (int p = 0; p < 4; p++) {
                *(uint32_t*)&Bs[nxt][br[p]][bc4[p] * 4]     = f2bf2(bL[p].x, bL[p].y);
                *(uint32_t*)&Bs[nxt][br[p]][bc4[p] * 4 + 2] = f2bf2(bL[p].z, bL[p].w);
            }
        }
        __syncthreads();
    }

    const float* bias = W + (size_t)IN_DIM * HIDDEN + n0;
    uint32_t* h1u = (uint32_t*)g_h1;
#pragma unroll
    for (int ni = 0; ni < 4; ni++) {
        int c = wn * 32 + ni * 8 + (lane & 3) * 2;
        float2 bb = *(const float2*)&bias[c];
#pragma unroll
        for (int mi = 0; mi < 2; mi++) {
            int r0 = wm * 32 + mi * 16 + (lane >> 2);
            if (r0 < rows) {
                float vx = fmaxf(acc[mi][ni][0] + bb.x, 0.f);
                float vy = fmaxf(acc[mi][ni][1] + bb.y, 0.f);
                h1u[((size_t)(start + r0) * HIDDEN + n0 + c) >> 1] = f2bf2(vx, vy);
            }
            int r1 = r0 + 8;
            if (r1 < rows) {
                float vx = fmaxf(acc[mi][ni][2] + bb.x, 0.f);
                float vy = fmaxf(acc[mi][ni][3] + bb.y, 0.f);
                h1u[((size_t)(start + r1) * HIDDEN + n0 + c) >> 1] = f2bf2(vx, vy);
            }
        }
    }
}

// ---------------------------------------------------------------------------
// Kernel 3: FC2 GEMM, N-split x4. grid (42, 4) = 168 blocks.
// Each block: 64 rows x 32 cols, full K=512 in 8 BK=64 phases, register-
// staged double buffering. Warp tile 16x16 (8 accum regs) -> light blocks.
// Epilogue: +bias, sigmoid, scatter via g_perm directly to out.
// ---------------------------------------------------------------------------
__global__ __launch_bounds__(256) void fc2_kernel(const float* __restrict__ tab,
                                                  float* __restrict__ out) {
    const int tile = blockIdx.x;
    const int nh   = blockIdx.y;                        // 0..3: 32-col slice
    const int rows = g_tileRows[tile];
    if (rows == 0) return;
    const int grp   = g_tileGroup[tile];
    const int start = g_tileStart[tile];
    const float* W  = tab + (size_t)grp * ((HIDDEN + 1) * STYLE) + nh * 32;

    __shared__ __align__(16) __nv_bfloat16 As[2][64][72];   // 64 + 8 pad
    __shared__ __align__(16) __nv_bfloat16 Bs[2][64][40];   // 32 + 8 pad
    __shared__ int rowIdx[64];

    const int t = threadIdx.x, lane = t & 31, warp = t >> 5;
    const int wm = warp >> 1, wn = warp & 1;            // 4 x 2 warps -> 16x16 warp tile

    if (t < 64) rowIdx[t] = (t < rows) ? g_perm[start + t] : 0;
    __syncthreads();

    // A: 64 rows x 64 bf16 per phase = 512 uint4, 2/thread
    int ar[2], aq[2];
#pragma unroll
    for (int p = 0; p < 2; p++) { int idx = t + p * 256; ar[p] = idx >> 3; aq[p] = idx & 7; }
    const __nv_bfloat16* h1b = g_h1 + (size_t)start * HIDDEN;
    // B: 64 k-rows x 8 float4 per phase = 512, 2/thread
    int br[2], bc4[2];
#pragma unroll
    for (int p = 0; p < 2; p++) { int idx = t + p * 256; br[p] = idx >> 3; bc4[p] = idx & 7; }

    float acc[2][4];
#pragma unroll
    for (int ni = 0; ni < 2; ni++)
#pragma unroll
        for (int j = 0; j < 4; j++) acc[ni][j] = 0.f;

    uint4 aL[2]; float4 bL[2];
    // Prologue: phase 0
#pragma unroll
    for (int p = 0; p < 2; p++)
        aL[p] = *(const uint4*)(h1b + (size_t)ar[p] * HIDDEN + aq[p] * 8);
#pragma unroll
    for (int p = 0; p < 2; p++)
        bL[p] = *(const float4*)&W[(size_t)br[p] * STYLE + bc4[p] * 4];
#pragma unroll
    for (int p = 0; p < 2; p++)
        *(uint4*)&As[0][ar[p]][aq[p] * 8] = aL[p];
#pragma unroll
    for (int p = 0; p < 2; p++) {
        *(uint32_t*)&Bs[0][br[p]][bc4[p] * 4]     = f2bf2(bL[p].x, bL[p].y);
        *(uint32_t*)&Bs[0][br[p]][bc4[p] * 4 + 2] = f2bf2(bL[p].z, bL[p].w);
    }
    __syncthreads();

    const int NPH = HIDDEN / 64;                        // 8
    for (int ph = 0; ph < NPH; ++ph) {
        const int cur = ph & 1;
        if (ph + 1 < NPH) {
            const int k0 = (ph + 1) * 64;
#pragma unroll
            for (int p = 0; p < 2; p++)
                aL[p] = *(const uint4*)(h1b + (size_t)ar[p] * HIDDEN + k0 + aq[p] * 8);
#pragma unroll
            for (int p = 0; p < 2; p++)
                bL[p] = *(const float4*)&W[(size_t)(k0 + br[p]) * STYLE + bc4[p] * 4];
        }

#pragma unroll
        for (int kh = 0; kh < 4; kh++) {
            uint32_t a[4], b[2][2];
            uint32_t sa = (uint32_t)__cvta_generic_to_shared(
                &As[cur][wm * 16 + (lane & 15)][kh * 16 + (lane >> 4) * 8]);
            ldsm_x4(a[0], a[1], a[2], a[3], sa);
            uint32_t sb = (uint32_t)__cvta_generic_to_shared(
                &Bs[cur][kh * 16 + (lane & 7) + ((lane >> 3) & 1) * 8]
                   [wn * 16 + (lane >> 4) * 8]);
            ldsm_x4_t(b[0][0], b[0][1], b[1][0], b[1][1], sb);
#pragma unroll
            for (int ni = 0; ni < 2; ni++)
                mma16816_c(acc[ni], a, b[ni]);
        }

        if (ph + 1 < NPH) {
            const int nxt = cur ^ 1;
#pragma unroll
            for (int p = 0; p < 2; p++)
                *(uint4*)&As[nxt][ar[p]][aq[p] * 8] = aL[p];
#pragma unroll
            for (int p = 0; p < 2; p++) {
                *(uint32_t*)&Bs[nxt][br[p]][bc4[p] * 4]     = f2bf2(bL[p].x, bL[p].y);
                *(uint32_t*)&Bs[nxt][br[p]][bc4[p] * 4 + 2] = f2bf2(bL[p].z, bL[p].w);
            }
        }
        __syncthreads();
    }

    // Epilogue: +bias, sigmoid, scatter fp32
    const float* bias = tab + (size_t)grp * ((HIDDEN + 1) * STYLE)
                      + (size_t)HIDDEN * STYLE + nh * 32;
#pragma unroll
    for (int ni = 0; ni < 2; ni++) {
        int c = wn * 16 + ni * 8 + (lane & 3) * 2;
        float2 bb = *(const float2*)&bias[c];
        int r0 = wm * 16 + (lane >> 2);
        if (r0 < rows) {
            int orow = rowIdx[r0];
            float2 v;
            v.x = 1.f / (1.f + __expf(-(acc[ni][0] + bb.x)));
            v.y = 1.f / (1.f + __expf(-(acc[ni][1] + bb.y)));
            *(float2*)&out[(size_t)orow * STYLE + nh * 32 + c] = v;
        }
        int r1 = r0 + 8;
        if (r1 < rows) {
            int orow = rowIdx[r1];
            float2 v;
            v.x = 1.f / (1.f + __expf(-(acc[ni][2] + bb.x)));
            v.y = 1.f / (1.f + __expf(-(acc[ni][3] + bb.y)));
            *(float2*)&out[(size_t)orow * STYLE + nh * 32 + c] = v;
        }
    }
}

extern "C" void kernel_launch(void* const* d_in, const int* in_sizes, int n_in,
                              void* d_out, int out_size) {
    const float* x         = (const float*)d_in[0];
    const int*   m         = (const int*)d_in[1];
    const float* fc1_table = (const float*)d_in[2];
    const float* fc2_table = (const float*)d_in[3];
    float*       out       = (float*)d_out;

    group_kernel<<<32, 256>>>(m);
    fc1_kernel<<<dim3(HIDDEN / 128, MAX_TILES), 256>>>(x, fc1_table);
    fc2_kernel<<<dim3(MAX_TILES, 4), 256>>>(fc2_table, out);
}

// round 17
// speedup vs baseline: 1.8000x; 1.0667x over previous
#include <cuda_runtime.h>
#include <cuda_bf16.h>
#include <math.h>
#include <stdint.h>

#define IN_DIM   784
#define HIDDEN   512
#define STYLE    128
#define BATCH    2048
#define NUM_LABELS 10

#define BM 64
#define MAX_TILES (BATCH / BM + NUM_LABELS)   // 42

// Scratch (no allocations allowed -> __device__ globals)
__device__ int   g_perm[BATCH];
__device__ int   g_tileGroup[MAX_TILES];
__device__ int   g_tileStart[MAX_TILES];
__device__ int   g_tileRows[MAX_TILES];
__device__ __nv_bfloat16 g_h1[(BATCH + 128) * HIDDEN];           // padded

// ---------------------------------------------------------------------------
// Helpers
// ---------------------------------------------------------------------------
__device__ __forceinline__ uint32_t f2bf2(float lo, float hi) {
    __nv_bfloat162 h = __floats2bfloat162_rn(lo, hi);
    return *reinterpret_cast<uint32_t*>(&h);
}

__device__ __forceinline__ void ldsm_x4(uint32_t& r0, uint32_t& r1, uint32_t& r2, uint32_t& r3,
                                        uint32_t saddr) {
    asm volatile("ldmatrix.sync.aligned.m8n8.x4.shared.b16 {%0,%1,%2,%3}, [%4];"
                 : "=r"(r0), "=r"(r1), "=r"(r2), "=r"(r3) : "r"(saddr));
}

__device__ __forceinline__ void ldsm_x4_t(uint32_t& r0, uint32_t& r1, uint32_t& r2, uint32_t& r3,
                                          uint32_t saddr) {
    asm volatile("ldmatrix.sync.aligned.m8n8.x4.trans.shared.b16 {%0,%1,%2,%3}, [%4];"
                 : "=r"(r0), "=r"(r1), "=r"(r2), "=r"(r3) : "r"(saddr));
}

__device__ __forceinline__ void mma16816_c(float* c, const uint32_t* a, const uint32_t* b) {
    asm volatile("mma.sync.aligned.m16n8k16.row.col.f32.bf16.bf16.f32 "
                 "{%0,%1,%2,%3}, {%4,%5,%6,%7}, {%8,%9}, {%0,%1,%2,%3};"
                 : "+f"(c[0]), "+f"(c[1]), "+f"(c[2]), "+f"(c[3])
                 : "r"(a[0]), "r"(a[1]), "r"(a[2]), "r"(a[3]), "r"(b[0]), "r"(b[1]));
}

// ---------------------------------------------------------------------------
// Kernel 1: grouping, 32 blocks (R15 de-serialized version) + PDL trigger.
// ---------------------------------------------------------------------------
__global__ void group_kernel(const int* __restrict__ m) {
    __shared__ uint16_t h[NUM_LABELS][257];
    __shared__ int cnt[NUM_LABELS];
    __shared__ int baseS[NUM_LABELS];
    __shared__ int ntBase[NUM_LABELS + 1];
    const int t = threadIdx.x, lane = t & 31, warp = t >> 5;

    int4 lv0 = ((const int4*)m)[t * 2];
    int4 lv1 = ((const int4*)m)[t * 2 + 1];
    int lab[8] = {lv0.x, lv0.y, lv0.z, lv0.w, lv1.x, lv1.y, lv1.z, lv1.w};

#pragma unroll
    for (int g = 0; g < NUM_LABELS; g++) {
        int c = 0;
#pragma unroll
        for (int j = 0; j < 8; j++) c += (lab[j] == g);
        h[g][t] = (uint16_t)c;
    }
    __syncthreads();

    for (int g = warp; g < NUM_LABELS; g += 8) {
        int s = 0;
#pragma unroll
        for (int j = 0; j < 8; j++) s += h[g][lane * 8 + j];
        int incl = s;
#pragma unroll
        for (int d = 1; d < 32; d <<= 1) {
            int v = __shfl_up_sync(0xffffffffu, incl, d);
            if (lane >= d) incl += v;
        }
        int run = incl - s;
#pragma unroll
        for (int j = 0; j < 8; j++) {
            int tt = lane * 8 + j;
            int v = h[g][tt];
            h[g][tt] = (uint16_t)run;
            run += v;
        }
        if (lane == 31) cnt[g] = run;
    }
    __syncthreads();

    if (warp == 0) {
        int c  = (lane < NUM_LABELS) ? cnt[lane] : 0;
        int inc = c;
#pragma unroll
        for (int d = 1; d < 32; d <<= 1) {
            int v = __shfl_up_sync(0xffffffffu, inc, d);
            if (lane >= d) inc += v;
        }
        if (lane < NUM_LABELS) baseS[lane] = inc - c;

        int nt  = (lane < NUM_LABELS) ? (c + BM - 1) >> 6 : 0;
        int incN = nt;
#pragma unroll
        for (int d = 1; d < 32; d <<= 1) {
            int v = __shfl_up_sync(0xffffffffu, incN, d);
            if (lane >= d) incN += v;
        }
        if (lane <= NUM_LABELS) ntBase[lane] = incN - nt;
    }
    __syncthreads();

    if (blockIdx.x == 0 && t < MAX_TILES) {
        int total = ntBase[NUM_LABELS];
        if (t < total) {
            int g = 0;
#pragma unroll
            for (int gg = 1; gg < NUM_LABELS; gg++)
                if (t >= ntBase[gg]) g = gg;
            int j = t - ntBase[g];
            g_tileGroup[t] = g;
            g_tileStart[t] = baseS[g] + j * BM;
            g_tileRows[t]  = min(BM, cnt[g] - j * BM);
        } else {
            g_tileRows[t] = 0;
        }
    }

    if ((t >> 3) == (int)blockIdx.x) {
#pragma unroll
        for (int j = 0; j < 8; j++) {
            int g = lab[j];
            int rank = 0;
#pragma unroll
            for (int j2 = 0; j2 < 8; j2++)
                if (j2 < j) rank += (lab[j2] == g);
            g_perm[baseS[g] + (int)h[g][t] + rank] = t * 8 + j;
        }
    }

#if __CUDA_ARCH__ >= 900
    cudaTriggerProgrammaticLaunchCompletion();
#endif
}

// ---------------------------------------------------------------------------
// Kernel 2: FC1 GEMM: 64x128 tile, BK=32, 256 thr, occ 2. (R8 body)
// PDL: grid-dep-sync at entry (overlaps launch with group), trigger at end.
// ---------------------------------------------------------------------------
__global__ __launch_bounds__(256, 2) void fc1_kernel(const float* __restrict__ x,
                                                     const float* __restrict__ tab) {
#if __CUDA_ARCH__ >= 900
    cudaGridDependencySynchronize();
#endif
    const int tile = blockIdx.y;
    const int rows = g_tileRows[tile];
    if (rows == 0) {
#if __CUDA_ARCH__ >= 900
        cudaTriggerProgrammaticLaunchCompletion();
#endif
        return;
    }
    const int grp   = g_tileGroup[tile];
    const int start = g_tileStart[tile];
    const int n0    = blockIdx.x * 128;
    const float* W  = tab + (size_t)grp * ((IN_DIM + 1) * HIDDEN);

    __shared__ __align__(16) __nv_bfloat16 As[2][64][40];
    __shared__ __align__(16) __nv_bfloat16 Bs[2][32][136];
    __shared__ int rowIdx[64];

    const int t = threadIdx.x, lane = t & 31, warp = t >> 5;
    const int wm = warp >> 2, wn = warp & 3;

    if (t < 64) rowIdx[t] = (t < rows) ? g_perm[start + t] : -1;
    __syncthreads();

    int ar[2], ac4[2], alim[2]; const float* aptr[2];
#pragma unroll
    for (int p = 0; p < 2; p++) {
        int idx = t + p * 256;
        ar[p] = idx >> 3; ac4[p] = idx & 7;
        int gr = rowIdx[ar[p]];
        aptr[p] = x + (size_t)max(gr, 0) * IN_DIM + ac4[p] * 4;
        alim[p] = (gr >= 0) ? (IN_DIM - ac4[p] * 4) : 0;
    }
    int br[4], bc4[4];
#pragma unroll
    for (int p = 0; p < 4; p++) { int idx = t + p * 256; br[p] = idx >> 5; bc4[p] = idx & 31; }

    float acc[2][4][4];
#pragma unroll
    for (int mi = 0; mi < 2; mi++)
#pragma unroll
        for (int ni = 0; ni < 4; ni++)
#pragma unroll
            for (int j = 0; j < 4; j++) acc[mi][ni][j] = 0.f;

    const float4 Z4 = make_float4(0.f, 0.f, 0.f, 0.f);
    float4 aL[2], bL[4];
#pragma unroll
    for (int p = 0; p < 2; p++)
        aL[p] = (alim[p] > 0) ? *(const float4*)(aptr[p]) : Z4;
#pragma unroll
    for (int p = 0; p < 4; p++)
        bL[p] = *(const float4*)&W[(size_t)br[p] * HIDDEN + n0 + bc4[p] * 4];
#pragma unroll
    for (int p = 0; p < 2; p++) {
        *(uint32_t*)&As[0][ar[p]][ac4[p] * 4]     = f2bf2(aL[p].x, aL[p].y);
        *(uint32_t*)&As[0][ar[p]][ac4[p] * 4 + 2] = f2bf2(aL[p].z, aL[p].w);
    }
#pragma unroll
    for (int p = 0; p < 4; p++) {
        *(uint32_t*)&Bs[0][br[p]][bc4[p] * 4]     = f2bf2(bL[p].x, bL[p].y);
        *(uint32_t*)&Bs[0][br[p]][bc4[p] * 4 + 2] = f2bf2(bL[p].z, bL[p].w);
    }
    __syncthreads();

    const int NIT = (IN_DIM + 31) / 32;    // 25
    for (int it = 0; it < NIT; ++it) {
        const int cur = it & 1;
        if (it + 1 < NIT) {
            const int k0 = (it + 1) * 32;
#pragma unroll
            for (int p = 0; p < 2; p++)
                aL[p] = (k0 < alim[p]) ? *(const float4*)(aptr[p] + k0) : Z4;
#pragma unroll
            for (int p = 0; p < 4; p++) {
                int kr = k0 + br[p];
                const float4 v = *(const float4*)&W[(size_t)min(kr, IN_DIM) * HIDDEN + n0 + bc4[p] * 4];
                bL[p] = (kr < IN_DIM) ? v : Z4;
            }
        }

        uint32_t a[2][2][4], b[2][4][2];
#pragma unroll
        for (int mi = 0; mi < 2; mi++)
#pragma unroll
            for (int kh = 0; kh < 2; kh++) {
                uint32_t sa = (uint32_t)__cvta_generic_to_shared(
                    &As[cur][wm * 32 + mi * 16 + (lane & 15)][kh * 16 + (lane >> 4) * 8]);
                ldsm_x4(a[mi][kh][0], a[mi][kh][1], a[mi][kh][2], a[mi][kh][3], sa);
            }
#pragma unroll
        for (int kh = 0; kh < 2; kh++)
#pragma unroll
            for (int half = 0; half < 2; half++) {
                uint32_t sb = (uint32_t)__cvta_generic_to_shared(
                    &Bs[cur][kh * 16 + (lane & 7) + ((lane >> 3) & 1) * 8]
                       [wn * 32 + half * 16 + (lane >> 4) * 8]);
                ldsm_x4_t(b[kh][2 * half][0], b[kh][2 * half][1],
                          b[kh][2 * half + 1][0], b[kh][2 * half + 1][1], sb);
            }
#pragma unroll
        for (int kh = 0; kh < 2; kh++)
#pragma unroll
            for (int mi = 0; mi < 2; mi++)
#pragma unroll
                for (int ni = 0; ni < 4; ni++)
                    mma16816_c(acc[mi][ni], a[mi][kh], b[kh][ni]);

        if (it + 1 < NIT) {
            const int nxt = cur ^ 1;
#pragma unroll
            for (int p = 0; p < 2; p++) {
                *(uint32_t*)&As[nxt][ar[p]][ac4[p] * 4]     = f2bf2(aL[p].x, aL[p].y);
                *(uint32_t*)&As[nxt][ar[p]][ac4[p] * 4 + 2] = f2bf2(aL[p].z, aL[p].w);
            }
#pragma unroll
            for (int p = 0; p < 4; p++) {
                *(uint32_t*)&Bs[nxt][br[p]][bc4[p] * 4]     = f2bf2(bL[p].x, bL[p].y);
                *(uint32_t*)&Bs[nxt][br[p]][bc4[p] * 4 + 2] = f2bf2(bL[p].z, bL[p].w);
            }
        }
        __syncthreads();
    }

    const float* bias = W + (size_t)IN_DIM * HIDDEN + n0;
    uint32_t* h1u = (uint32_t*)g_h1;
#pragma unroll
    for (int ni = 0; ni < 4; ni++) {
        int c = wn * 32 + ni * 8 + (lane & 3) * 2;
        float2 bb = *(const float2*)&bias[c];
#pragma unroll
        for (int mi = 0; mi < 2; mi++) {
            int r0 = wm * 32 + mi * 16 + (lane >> 2);
            if (r0 < rows) {
                float vx = fmaxf(acc[mi][ni][0] + bb.x, 0.f);
                float vy = fmaxf(acc[mi][ni][1] + bb.y, 0.f);
                h1u[((size_t)(start + r0) * HIDDEN + n0 + c) >> 1] = f2bf2(vx, vy);
            }
            int r1 = r0 + 8;
            if (r1 < rows) {
                float vx = fmaxf(acc[mi][ni][2] + bb.x, 0.f);
                float vy = fmaxf(acc[mi][ni][3] + bb.y, 0.f);
                h1u[((size_t)(start + r1) * HIDDEN + n0 + c) >> 1] = f2bf2(vx, vy);
            }
        }
    }

#if __CUDA_ARCH__ >= 900
    cudaTriggerProgrammaticLaunchCompletion();
#endif
}

// ---------------------------------------------------------------------------
// Kernel 3: FC2 GEMM, N-split x4 (R15 body). PDL: pre-sync section loads the
// phase-0 B tile (weights; depend only on group, already complete) and
// rowIdx, THEN grid-dep-syncs on fc1 before touching g_h1.
// ---------------------------------------------------------------------------
__global__ __launch_bounds__(256) void fc2_kernel(const float* __restrict__ tab,
                                                  float* __restrict__ out) {
    const int tile = blockIdx.x;
    const int nh   = blockIdx.y;                        // 0..3: 32-col slice
    const int rows = g_tileRows[tile];
    if (rows == 0) {
#if __CUDA_ARCH__ >= 900
        cudaGridDependencySynchronize();
#endif
        return;
    }
    const int grp   = g_tileGroup[tile];
    const int start = g_tileStart[tile];
    const float* W  = tab + (size_t)grp * ((HIDDEN + 1) * STYLE) + nh * 32;

    __shared__ __align__(16) __nv_bfloat16 As[2][64][72];   // 64 + 8 pad
    __shared__ __align__(16) __nv_bfloat16 Bs[2][64][40];   // 32 + 8 pad
    __shared__ int rowIdx[64];

    const int t = threadIdx.x, lane = t & 31, warp = t >> 5;
    const int wm = warp >> 1, wn = warp & 1;            // 4 x 2 warps -> 16x16 warp tile

    if (t < 64) rowIdx[t] = (t < rows) ? g_perm[start + t] : 0;

    // per-thread load coords
    int ar[2], aq[2];
#pragma unroll
    for (int p = 0; p < 2; p++) { int idx = t + p * 256; ar[p] = idx >> 3; aq[p] = idx & 7; }
    const __nv_bfloat16* h1b = g_h1 + (size_t)start * HIDDEN;
    int br[2], bc4[2];
#pragma unroll
    for (int p = 0; p < 2; p++) { int idx = t + p * 256; br[p] = idx >> 3; bc4[p] = idx & 7; }

    float acc[2][4];
#pragma unroll
    for (int ni = 0; ni < 2; ni++)
#pragma unroll
        for (int j = 0; j < 4; j++) acc[ni][j] = 0.f;

    // ---- pre-sync: phase-0 B tile (weights, independent of fc1) -----------
    {
        float4 b0[2];
#pragma unroll
        for (int p = 0; p < 2; p++)
            b0[p] = *(const float4*)&W[(size_t)br[p] * STYLE + bc4[p] * 4];
#pragma unroll
        for (int p = 0; p < 2; p++) {
            *(uint32_t*)&Bs[0][br[p]][bc4[p] * 4]     = f2bf2(b0[p].x, b0[p].y);
            *(uint32_t*)&Bs[0][br[p]][bc4[p] * 4 + 2] = f2bf2(b0[p].z, b0[p].w);
        }
    }

#if __CUDA_ARCH__ >= 900
    cudaGridDependencySynchronize();     // fc1's g_h1 now visible
#endif

    uint4 aL[2]; float4 bL[2];
#pragma unroll
    for (int p = 0; p < 2; p++)
        aL[p] = *(const uint4*)(h1b + (size_t)ar[p] * HIDDEN + aq[p] * 8);
#pragma unroll
    for (int p = 0; p < 2; p++)
        *(uint4*)&As[0][ar[p]][aq[p] * 8] = aL[p];
    __syncthreads();

    const int NPH = HIDDEN / 64;                        // 8
    for (int ph = 0; ph < NPH; ++ph) {
        const int cur = ph & 1;
        if (ph + 1 < NPH) {
            const int k0 = (ph + 1) * 64;
#pragma unroll
            for (int p = 0; p < 2; p++)
                aL[p] = *(const uint4*)(h1b + (size_t)ar[p] * HIDDEN + k0 + aq[p] * 8);
#pragma unroll
            for (int p = 0; p < 2; p++)
                bL[p] = *(const float4*)&W[(size_t)(k0 + br[p]) * STYLE + bc4[p] * 4];
        }

#pragma unroll
        for (int kh = 0; kh < 4; kh++) {
            uint32_t a[4], b[2][2];
            uint32_t sa = (uint32_t)__cvta_generic_to_shared(
                &As[cur][wm * 16 + (lane & 15)][kh * 16 + (lane >> 4) * 8]);
            ldsm_x4(a[0], a[1], a[2], a[3], sa);
            uint32_t sb = (uint32_t)__cvta_generic_to_shared(
                &Bs[cur][kh * 16 + (lane & 7) + ((lane >> 3) & 1) * 8]
                   [wn * 16 + (lane >> 4) * 8]);
            ldsm_x4_t(b[0][0], b[0][1], b[1][0], b[1][1], sb);
#pragma unroll
            for (int ni = 0; ni < 2; ni++)
                mma16816_c(acc[ni], a, b[ni]);
        }

        if (ph + 1 < NPH) {
            const int nxt = cur ^ 1;
#pragma unroll
            for (int p = 0; p < 2; p++)
                *(uint4*)&As[nxt][ar[p]][aq[p] * 8] = aL[p];
#pragma unroll
            for (int p = 0; p < 2; p++) {
                *(uint32_t*)&Bs[nxt][br[p]][bc4[p] * 4]     = f2bf2(bL[p].x, bL[p].y);
                *(uint32_t*)&Bs[nxt][br[p]][bc4[p] * 4 + 2] = f2bf2(bL[p].z, bL[p].w);
            }
        }
        __syncthreads();
    }

    // Epilogue: +bias, sigmoid, scatter fp32
    const float* bias = tab + (size_t)grp * ((HIDDEN + 1) * STYLE)
                      + (size_t)HIDDEN * STYLE + nh * 32;
#pragma unroll
    for (int ni = 0; ni < 2; ni++) {
        int c = wn * 16 + ni * 8 + (lane & 3) * 2;
        float2 bb = *(const float2*)&bias[c];
        int r0 = wm * 16 + (lane >> 2);
        if (r0 < rows) {
            int orow = rowIdx[r0];
            float2 v;
            v.x = 1.f / (1.f + __expf(-(acc[ni][0] + bb.x)));
            v.y = 1.f / (1.f + __expf(-(acc[ni][1] + bb.y)));
            *(float2*)&out[(size_t)orow * STYLE + nh * 32 + c] = v;
        }
        int r1 = r0 + 8;
        if (r1 < rows) {
            int orow = rowIdx[r1];
            float2 v;
            v.x = 1.f / (1.f + __expf(-(acc[ni][2] + bb.x)));
            v.y = 1.f / (1.f + __expf(-(acc[ni][3] + bb.y)));
            *(float2*)&out[(size_t)orow * STYLE + nh * 32 + c] = v;
        }
    }
}

extern "C" void kernel_launch(void* const* d_in, const int* in_sizes, int n_in,
                              void* d_out, int out_size) {
    const float* x         = (const float*)d_in[0];
    const int*   m         = (const int*)d_in[1];
    const float* fc1_table = (const float*)d_in[2];
    const float* fc2_table = (const float*)d_in[3];
    float*       out       = (float*)d_out;

    group_kernel<<<32, 256>>>(m);

    cudaLaunchAttribute attr[1];
    attr[0].id = cudaLaunchAttributeProgrammaticStreamSerialization;
    attr[0].val.programmaticStreamSerializationAllowed = 1;

    {
        cudaLaunchConfig_t cfg = {};
        cfg.gridDim  = dim3(HIDDEN / 128, MAX_TILES);
        cfg.blockDim = dim3(256);
        cfg.attrs    = attr;
        cfg.numAttrs = 1;
        cudaLaunchKernelEx(&cfg, fc1_kernel, x, fc1_table);
    }
    {
        cudaLaunchConfig_t cfg = {};
        cfg.gridDim  = dim3(MAX_TILES, 4);
        cfg.blockDim = dim3(256);
        cfg.attrs    = attr;
        cfg.numAttrs = 1;
        cudaLaunchKernelEx(&cfg, fc2_kernel, fc2_table, out);
    }
}